// round 7
// baseline (speedup 1.0000x reference)
#include <cuda_runtime.h>
#include <cuda_bf16.h>
#include <cstdint>

#define BB 8
#define CC 512
#define TT 2048
#define EE 512
#define LN_EPS 1e-5f

typedef __nv_bfloat16 bf16;

// ------------------------------------------------------------------
// scratch (device globals — allocation-free rule)
// ------------------------------------------------------------------
__device__ float g_resid[BB * TT * CC];
__device__ bf16  g_resid_h[BB * TT * CC];
__device__ bf16  g_resid_l[BB * TT * CC];
__device__ bf16  g_q_h[BB * TT * EE];
__device__ bf16  g_q_l[BB * TT * EE];
__device__ bf16  g_k_h[BB * TT * EE];
__device__ bf16  g_k_l[BB * TT * EE];
__device__ bf16  g_vt_h[BB * EE * TT];   // v transposed: [B][E][T]
__device__ bf16  g_vt_l[BB * EE * TT];
__device__ bf16  g_attn_h[(size_t)BB * TT * TT];
__device__ bf16  g_att_h[BB * TT * EE];
__device__ bf16  g_att_l[BB * TT * EE];
__device__ float g_h[BB * TT * CC];
__device__ bf16  g_WqT_h[EE * CC], g_WqT_l[EE * CC];  // [E,C] = Wq^T
__device__ bf16  g_WkT_h[EE * CC], g_WkT_l[EE * CC];
__device__ bf16  g_WvT_h[EE * CC], g_WvT_l[EE * CC];
__device__ bf16  g_WoT_h[CC * EE], g_WoT_l[CC * EE];  // [C,E] = Wo^T

// ------------------------------------------------------------------
// low-level helpers (family-portable ISA only: ldmatrix / mma.sync / cp.async)
// ------------------------------------------------------------------
__device__ __forceinline__ uint32_t smem_u32(const void* p) {
    uint32_t a;
    asm("{ .reg .u64 t; cvta.to.shared.u64 t, %1; cvt.u32.u64 %0, t; }" : "=r"(a) : "l"(p));
    return a;
}

__device__ __forceinline__ uint32_t swz64(uint32_t o) { return o ^ ((o >> 3) & 0x30); }

#define CP16(dst, src) \
    asm volatile("cp.async.cg.shared.global [%0], [%1], 16;" :: "r"(dst), "l"(src))
#define CP_COMMIT() asm volatile("cp.async.commit_group;" ::: "memory")
#define CP_WAIT(n)  asm volatile("cp.async.wait_group %0;" :: "n"(n) : "memory")

__device__ __forceinline__ void ldsm4(uint32_t* r, uint32_t addr) {
    asm volatile("ldmatrix.sync.aligned.m8n8.x4.shared.b16 {%0,%1,%2,%3}, [%4];"
                 : "=r"(r[0]), "=r"(r[1]), "=r"(r[2]), "=r"(r[3]) : "r"(addr));
}

__device__ __forceinline__ void mma_bf16(float* c, const uint32_t* a,
                                         uint32_t b0, uint32_t b1) {
    asm volatile(
        "mma.sync.aligned.m16n8k16.row.col.f32.bf16.bf16.f32 "
        "{%0,%1,%2,%3}, {%4,%5,%6,%7}, {%8,%9}, {%0,%1,%2,%3};"
        : "+f"(c[0]), "+f"(c[1]), "+f"(c[2]), "+f"(c[3])
        : "r"(a[0]), "r"(a[1]), "r"(a[2]), "r"(a[3]), "r"(b0), "r"(b1));
}

__device__ __forceinline__ void split2(float v, bf16& h, bf16& l) {
    h = __float2bfloat16(v);
    l = __float2bfloat16(v - __bfloat162float(h));
}

// ------------------------------------------------------------------
// HMMA GEMM: D[128m x 128n] = sum of selected split terms of (Ah+Al)·(Bh+Bl)^T
// Terms: AhBh always; + AhBl if USE_BL; + AlBh if USE_AL.
// A row-major [M,K], B row-major [N,K]. BK=32.
// 512 threads, 16 warps as 4(m) x 4(n); warp tile 32x32.
// 3-stage cp.async pipeline, ONE barrier per chunk.
// ------------------------------------------------------------------
#define TILE_B (128 * 32 * 2)          // 8 KB per bf16 tile
#define CHUNK_B (4 * TILE_B)           // 32 KB slots (Ah,Al,Bh,Bl; unused slots not loaded)
#define NSTAGE 3
#define GEMM_SMEM_REQ (NSTAGE * CHUNK_B)   // 96 KB (epilogue stage 66KB reuses it)

enum { EPI_F32 = 0, EPI_BIAS_SPLIT = 1, EPI_BIAS_SPLIT_T = 2, EPI_SPLIT = 3, EPI_F32_BIAS_RES = 4 };

template <int EPI, int USE_AL, int USE_BL>
__global__ __launch_bounds__(512)
void hmma_gemm(const bf16* __restrict__ Ah, const bf16* __restrict__ Al, int ldA, size_t sA,
               const bf16* __restrict__ Bh, const bf16* __restrict__ Bl, int ldB, size_t sB,
               const float* __restrict__ bias, const float* __restrict__ res,
               float* __restrict__ Cf, bf16* __restrict__ Ch, bf16* __restrict__ Cl,
               int ldc, size_t sC, int K) {
    extern __shared__ char sm[];
    uint32_t smu = smem_u32(sm);

    const int tid = threadIdx.x;
    const int w = tid >> 5, lane = tid & 31;
    const int bz = blockIdx.z;
    const int m0 = blockIdx.y * 128;
    const int n0 = blockIdx.x * 128;

    const bf16* pAh = Ah + (size_t)bz * sA + (size_t)m0 * ldA;
    const bf16* pAl = USE_AL ? (Al + (size_t)bz * sA + (size_t)m0 * ldA) : nullptr;
    const bf16* pBh = Bh + (size_t)bz * sB + (size_t)n0 * ldB;
    const bf16* pBl = USE_BL ? (Bl + (size_t)bz * sB + (size_t)n0 * ldB) : nullptr;

    // loader: 512 segments per tile, 512 threads -> 1 cp.async per tile each
    const int lrow = tid >> 2, lcs = tid & 3;
    const uint32_t loff = swz64((uint32_t)(lrow * 64 + lcs * 16));
    auto load_chunk = [&](int buf, int k0) {
        uint32_t base = smu + (uint32_t)buf * CHUNK_B;
        CP16(base + 0 * TILE_B + loff, pAh + (size_t)lrow * ldA + k0 + lcs * 8);
        if (USE_AL) CP16(base + 1 * TILE_B + loff, pAl + (size_t)lrow * ldA + k0 + lcs * 8);
        CP16(base + 2 * TILE_B + loff, pBh + (size_t)lrow * ldB + k0 + lcs * 8);
        if (USE_BL) CP16(base + 3 * TILE_B + loff, pBl + (size_t)lrow * ldB + k0 + lcs * 8);
    };

    // warp layout: 4 (m) x 4 (n); warp tile 32 x 32
    const int wm = w >> 2, wn = w & 3;
    const int lr = lane & 7;
    const int r8 = (lane >> 3) & 1;
    const int chi = lane >> 4;

    uint32_t offA[2][2], offB[2][2];
#pragma unroll
    for (int mt = 0; mt < 2; mt++)
#pragma unroll
        for (int ks = 0; ks < 2; ks++)
            offA[mt][ks] = swz64((uint32_t)((wm * 32 + mt * 16 + r8 * 8 + lr) * 64 + (2 * ks + chi) * 16));
#pragma unroll
    for (int nt = 0; nt < 2; nt++)
#pragma unroll
        for (int ks = 0; ks < 2; ks++)
            offB[nt][ks] = swz64((uint32_t)((wn * 32 + nt * 16 + r8 * 8 + lr) * 64 + (2 * ks + chi) * 16));

    float acc[2][4][4];   // [mt][nt*2+nh][quad]
#pragma unroll
    for (int i = 0; i < 2; i++)
#pragma unroll
        for (int j = 0; j < 4; j++)
#pragma unroll
            for (int q = 0; q < 4; q++) acc[i][j][q] = 0.f;

    const int nch = K / 32;
    load_chunk(0, 0);
    CP_COMMIT();
    if (nch > 1) load_chunk(1, 32);
    CP_COMMIT();

    int buf = 0;
    for (int c = 0; c < nch; c++) {
        CP_WAIT(1);          // group c complete (c+2 not yet committed)
        __syncthreads();     // orders prior-iter reads of buf (c+2)%3 before its overwrite

        if (c + 2 < nch) {
            int fb = buf + 2;
            if (fb >= NSTAGE) fb -= NSTAGE;
            load_chunk(fb, (c + 2) * 32);
        }
        CP_COMMIT();         // always commit (possibly empty) -> wait(1) stays exact

        uint32_t bu = smu + (uint32_t)buf * CHUNK_B;
#pragma unroll
        for (int ks = 0; ks < 2; ks++) {
            uint32_t afh[2][4], afl[2][4], bfh[2][4], bfl[2][4];
#pragma unroll
            for (int mt = 0; mt < 2; mt++) {
                ldsm4(afh[mt], bu + 0 * TILE_B + offA[mt][ks]);
                if (USE_AL) ldsm4(afl[mt], bu + 1 * TILE_B + offA[mt][ks]);
            }
#pragma unroll
            for (int nt = 0; nt < 2; nt++) {
                ldsm4(bfh[nt], bu + 2 * TILE_B + offB[nt][ks]);
                if (USE_BL) ldsm4(bfl[nt], bu + 3 * TILE_B + offB[nt][ks]);
            }
#pragma unroll
            for (int mt = 0; mt < 2; mt++) {
#pragma unroll
                for (int nt = 0; nt < 2; nt++) {
                    mma_bf16(acc[mt][nt * 2 + 0], afh[mt], bfh[nt][0], bfh[nt][2]);
                    mma_bf16(acc[mt][nt * 2 + 1], afh[mt], bfh[nt][1], bfh[nt][3]);
                    if (USE_BL) {
                        mma_bf16(acc[mt][nt * 2 + 0], afh[mt], bfl[nt][0], bfl[nt][2]);
                        mma_bf16(acc[mt][nt * 2 + 1], afh[mt], bfl[nt][1], bfl[nt][3]);
                    }
                    if (USE_AL) {
                        mma_bf16(acc[mt][nt * 2 + 0], afl[mt], bfh[nt][0], bfh[nt][2]);
                        mma_bf16(acc[mt][nt * 2 + 1], afl[mt], bfh[nt][1], bfh[nt][3]);
                    }
                }
            }
        }
        buf++;
        if (buf == NSTAGE) buf = 0;
    }
    __syncthreads();   // all compute done before st overwrites buffers

    // ---- epilogue: accumulators -> staged smem [128][129] fp32 -> gmem ----
    float* st = (float*)sm;
    {
        int g = lane >> 2, t4 = lane & 3;
#pragma unroll
        for (int mt = 0; mt < 2; mt++) {
            int r = wm * 32 + mt * 16 + g;
#pragma unroll
            for (int j = 0; j < 4; j++) {
                int ccol = wn * 32 + j * 8 + 2 * t4;
                st[r * 129 + ccol]           = acc[mt][j][0];
                st[r * 129 + ccol + 1]       = acc[mt][j][1];
                st[(r + 8) * 129 + ccol]     = acc[mt][j][2];
                st[(r + 8) * 129 + ccol + 1] = acc[mt][j][3];
            }
        }
    }
    __syncthreads();

    if (EPI == EPI_BIAS_SPLIT_T) {
        // transposed split store: dest vt[b][e][t]
#pragma unroll 4
        for (int it = 0; it < 8; it++) {
            int col = w + 16 * it;
            float bv = bias[n0 + col];
#pragma unroll
            for (int j = 0; j < 4; j++) {
                int row = lane + 32 * j;
                float v = st[row * 129 + col] + bv;
                size_t m = (size_t)m0 + row;
                int bb_ = (int)(m / TT);
                int t = (int)(m % TT);
                size_t off = ((size_t)bb_ * EE + (n0 + col)) * TT + t;
                bf16 h, l; split2(v, h, l);
                Ch[off] = h;
                Cl[off] = l;
            }
        }
    } else {
        float bv[4];
#pragma unroll
        for (int cb = 0; cb < 4; cb++)
            bv[cb] = (EPI == EPI_BIAS_SPLIT || EPI == EPI_F32_BIAS_RES) ? bias[n0 + lane + 32 * cb] : 0.f;

#pragma unroll 2
        for (int rr = 0; rr < 8; rr++) {
            int row = w * 8 + rr;
            size_t m = (size_t)m0 + row;
#pragma unroll
            for (int cb = 0; cb < 4; cb++) {
                int col = lane + 32 * cb;
                float v = st[row * 129 + col] + bv[cb];
                size_t off = (size_t)bz * sC + m * ldc + n0 + col;
                if (EPI == EPI_F32) {
                    Cf[off] = v;
                } else if (EPI == EPI_F32_BIAS_RES) {
                    Cf[off] = v + res[m * ldc + n0 + col];
                } else {  // split row-major
                    bf16 h, l; split2(v, h, l);
                    Ch[off] = h;
                    Cl[off] = l;
                }
            }
        }
    }
}

// ------------------------------------------------------------------
// transpose + split: x[B,C,T] -> resid[B,T,C] (fp32 + hi/lo bf16)
// ------------------------------------------------------------------
__global__ __launch_bounds__(256)
void transpose_split(const float* __restrict__ x, float* __restrict__ r,
                     bf16* __restrict__ rh, bf16* __restrict__ rl) {
    __shared__ float tile[32][33];
    int b = blockIdx.z;
    int t0 = blockIdx.x * 32;
    int c0 = blockIdx.y * 32;
    const float* xb = x + (size_t)b * CC * TT;
    size_t ob = (size_t)b * TT * CC;
    int tx = threadIdx.x, ty = threadIdx.y;
#pragma unroll
    for (int i = ty; i < 32; i += 8)
        tile[i][tx] = xb[(size_t)(c0 + i) * TT + t0 + tx];
    __syncthreads();
#pragma unroll
    for (int i = ty; i < 32; i += 8) {
        float v = tile[tx][i];
        size_t off = ob + (size_t)(t0 + i) * CC + c0 + tx;
        r[off] = v;
        bf16 h, l; split2(v, h, l);
        rh[off] = h;
        rl[off] = l;
    }
}

// W [512,512] -> W^T hi/lo [512,512]
__global__ __launch_bounds__(256)
void wsplit(const float* __restrict__ W, bf16* __restrict__ Th, bf16* __restrict__ Tl) {
    __shared__ float tile[32][33];
    int k0 = blockIdx.y * 32, n0 = blockIdx.x * 32;
    int tx = threadIdx.x, ty = threadIdx.y;
#pragma unroll
    for (int i = ty; i < 32; i += 8)
        tile[i][tx] = W[(size_t)(k0 + i) * 512 + n0 + tx];
    __syncthreads();
#pragma unroll
    for (int i = ty; i < 32; i += 8) {
        float v = tile[tx][i];  // W[k0+tx][n0+i]
        size_t off = (size_t)(n0 + i) * 512 + k0 + tx;
        bf16 h, l; split2(v, h, l);
        Th[off] = h;
        Tl[off] = l;
    }
}

// ------------------------------------------------------------------
// softmax (in-place fp32) + emit hi bf16 only (lo not needed downstream)
// ------------------------------------------------------------------
__global__ __launch_bounds__(256)
void softmax_split(float* __restrict__ attn, bf16* __restrict__ ah) {
    size_t ro = (size_t)blockIdx.x * TT;
    float* row = attn + ro;
    int t = threadIdx.x;
    float vals[8];
    float m = -1e30f;
#pragma unroll
    for (int j = 0; j < 8; j++) {
        vals[j] = row[t + 256 * j];
        m = fmaxf(m, vals[j]);
    }
#pragma unroll
    for (int o = 16; o; o >>= 1) m = fmaxf(m, __shfl_xor_sync(0xffffffffu, m, o));
    __shared__ float smax[8], ssum[8];
    if ((t & 31) == 0) smax[t >> 5] = m;
    __syncthreads();
    float rm = smax[0];
#pragma unroll
    for (int i = 1; i < 8; i++) rm = fmaxf(rm, smax[i]);

    float s = 0.f;
#pragma unroll
    for (int j = 0; j < 8; j++) {
        vals[j] = expf(vals[j] - rm);
        s += vals[j];
    }
#pragma unroll
    for (int o = 16; o; o >>= 1) s += __shfl_xor_sync(0xffffffffu, s, o);
    if ((t & 31) == 0) ssum[t >> 5] = s;
    __syncthreads();
    float tot = 0.f;
#pragma unroll
    for (int i = 0; i < 8; i++) tot += ssum[i];
    float inv = 1.f / tot;

#pragma unroll
    for (int j = 0; j < 8; j++) {
        float v = vals[j] * inv;
        row[t + 256 * j] = v;
        ah[ro + t + 256 * j] = __float2bfloat16(v);
    }
}

// ------------------------------------------------------------------
// LayerNorm over C=512
// ------------------------------------------------------------------
__global__ __launch_bounds__(128)
void ln_kernel(const float* __restrict__ h, const float* __restrict__ gamma,
               const float* __restrict__ beta, float* __restrict__ out) {
    const float* hr = h + (size_t)blockIdx.x * CC;
    int t = threadIdx.x;
    float4 v = ((const float4*)hr)[t];

    float s = v.x + v.y + v.z + v.w;
#pragma unroll
    for (int o = 16; o; o >>= 1) s += __shfl_xor_sync(0xffffffffu, s, o);
    __shared__ float s1[4], s2[4];
    if ((t & 31) == 0) s1[t >> 5] = s;
    __syncthreads();
    float mu = (s1[0] + s1[1] + s1[2] + s1[3]) * (1.f / CC);

    float dx = v.x - mu, dy = v.y - mu, dz = v.z - mu, dw = v.w - mu;
    float q = dx * dx + dy * dy + dz * dz + dw * dw;
#pragma unroll
    for (int o = 16; o; o >>= 1) q += __shfl_xor_sync(0xffffffffu, q, o);
    if ((t & 31) == 0) s2[t >> 5] = q;
    __syncthreads();
    float var = (s2[0] + s2[1] + s2[2] + s2[3]) * (1.f / CC);
    float inv = rsqrtf(var + LN_EPS);

    float4 g = ((const float4*)gamma)[t];
    float4 b = ((const float4*)beta)[t];
    float4 o4;
    o4.x = dx * inv * g.x + b.x;
    o4.y = dy * inv * g.y + b.y;
    o4.z = dz * inv * g.z + b.z;
    o4.w = dw * inv * g.w + b.w;
    ((float4*)(out + (size_t)blockIdx.x * CC))[t] = o4;
}

// ------------------------------------------------------------------
// launch
// ------------------------------------------------------------------
extern "C" void kernel_launch(void* const* d_in, const int* in_sizes, int n_in,
                              void* d_out, int out_size) {
    const float* x     = (const float*)d_in[0];
    const float* Wq    = (const float*)d_in[1];
    const float* bq    = (const float*)d_in[2];
    const float* Wk    = (const float*)d_in[3];
    const float* bk    = (const float*)d_in[4];
    const float* Wv    = (const float*)d_in[5];
    const float* bv    = (const float*)d_in[6];
    const float* Wo    = (const float*)d_in[7];
    const float* bo    = (const float*)d_in[8];
    const float* gamma = (const float*)d_in[9];
    const float* beta  = (const float*)d_in[10];

    float* out = (float*)d_out;
    float* attn = out;
    float* final_out = out + (size_t)BB * TT * TT;

    float *resid, *hbuf;
    bf16 *rh, *rl, *qh, *ql, *kh, *kl, *vth, *vtl, *anh, *ath, *atl;
    bf16 *wqh, *wql, *wkh, *wkl, *wvh, *wvl, *woh, *wol;
    cudaGetSymbolAddress((void**)&resid, g_resid);
    cudaGetSymbolAddress((void**)&hbuf, g_h);
    cudaGetSymbolAddress((void**)&rh, g_resid_h);
    cudaGetSymbolAddress((void**)&rl, g_resid_l);
    cudaGetSymbolAddress((void**)&qh, g_q_h);
    cudaGetSymbolAddress((void**)&ql, g_q_l);
    cudaGetSymbolAddress((void**)&kh, g_k_h);
    cudaGetSymbolAddress((void**)&kl, g_k_l);
    cudaGetSymbolAddress((void**)&vth, g_vt_h);
    cudaGetSymbolAddress((void**)&vtl, g_vt_l);
    cudaGetSymbolAddress((void**)&anh, g_attn_h);
    cudaGetSymbolAddress((void**)&ath, g_att_h);
    cudaGetSymbolAddress((void**)&atl, g_att_l);
    cudaGetSymbolAddress((void**)&wqh, g_WqT_h);
    cudaGetSymbolAddress((void**)&wql, g_WqT_l);
    cudaGetSymbolAddress((void**)&wkh, g_WkT_h);
    cudaGetSymbolAddress((void**)&wkl, g_WkT_l);
    cudaGetSymbolAddress((void**)&wvh, g_WvT_h);
    cudaGetSymbolAddress((void**)&wvl, g_WvT_l);
    cudaGetSymbolAddress((void**)&woh, g_WoT_h);
    cudaGetSymbolAddress((void**)&wol, g_WoT_l);

    cudaFuncSetAttribute(hmma_gemm<EPI_BIAS_SPLIT, 1, 1>,   cudaFuncAttributeMaxDynamicSharedMemorySize, GEMM_SMEM_REQ);
    cudaFuncSetAttribute(hmma_gemm<EPI_BIAS_SPLIT_T, 0, 1>, cudaFuncAttributeMaxDynamicSharedMemorySize, GEMM_SMEM_REQ);
    cudaFuncSetAttribute(hmma_gemm<EPI_F32, 1, 1>,          cudaFuncAttributeMaxDynamicSharedMemorySize, GEMM_SMEM_REQ);
    cudaFuncSetAttribute(hmma_gemm<EPI_SPLIT, 0, 1>,        cudaFuncAttributeMaxDynamicSharedMemorySize, GEMM_SMEM_REQ);
    cudaFuncSetAttribute(hmma_gemm<EPI_F32_BIAS_RES, 1, 0>, cudaFuncAttributeMaxDynamicSharedMemorySize, GEMM_SMEM_REQ);

    // 1. transpose + split
    transpose_split<<<dim3(TT / 32, CC / 32, BB), dim3(32, 8)>>>(x, resid, rh, rl);

    // 2. weight transpose + split (tiny)
    wsplit<<<dim3(16, 16), dim3(32, 8)>>>(Wq, wqh, wql);
    wsplit<<<dim3(16, 16), dim3(32, 8)>>>(Wk, wkh, wkl);
    wsplit<<<dim3(16, 16), dim3(32, 8)>>>(Wv, wvh, wvl);
    wsplit<<<dim3(16, 16), dim3(32, 8)>>>(Wo, woh, wol);

    // 3. QKV projections: [16384,512] x [512,512]^T (stored [E,C])
    {
        dim3 grid(EE / 128, (BB * TT) / 128, 1);
        // q, k: full 3-term (feed the logit path)
        hmma_gemm<EPI_BIAS_SPLIT, 1, 1><<<grid, 512, GEMM_SMEM_REQ>>>(
            rh, rl, CC, 0, wqh, wql, CC, 0, bq, nullptr,
            nullptr, qh, ql, EE, 0, CC);
        hmma_gemm<EPI_BIAS_SPLIT, 1, 1><<<grid, 512, GEMM_SMEM_REQ>>>(
            rh, rl, CC, 0, wkh, wkl, CC, 0, bk, nullptr,
            nullptr, kh, kl, EE, 0, CC);
        // v: 2-term (drop resid_lo x W term)
        hmma_gemm<EPI_BIAS_SPLIT_T, 0, 1><<<grid, 512, GEMM_SMEM_REQ>>>(
            rh, nullptr, CC, 0, wvh, wvl, CC, 0, bv, nullptr,
            nullptr, vth, vtl, EE, 0, CC);
    }

    // 4. energy = q @ k^T (3-term) -> fp32 logits in attn output region
    {
        dim3 grid(TT / 128, TT / 128, BB);
        hmma_gemm<EPI_F32, 1, 1><<<grid, 512, GEMM_SMEM_REQ>>>(
            qh, ql, EE, (size_t)TT * EE, kh, kl, EE, (size_t)TT * EE,
            nullptr, nullptr, attn, nullptr, nullptr, TT, (size_t)TT * TT, EE);
    }

    // 5. softmax in-place + emit hi only
    softmax_split<<<BB * TT, 256>>>(attn, anh);

    // 6. attended = attn_hi @ (v_hi + v_lo)  (2-term; B operand = v^T [E,T])
    {
        dim3 grid(EE / 128, TT / 128, BB);
        hmma_gemm<EPI_SPLIT, 0, 1><<<grid, 512, GEMM_SMEM_REQ>>>(
            anh, nullptr, TT, (size_t)TT * TT, vth, vtl, TT, (size_t)EE * TT,
            nullptr, nullptr, nullptr, ath, atl, EE, (size_t)TT * EE, TT);
    }

    // 7. h = (att_hi + att_lo) @ Wo_hi + bo + resid (2-term, drop Wo_lo)
    {
        dim3 grid(CC / 128, (BB * TT) / 128, 1);
        hmma_gemm<EPI_F32_BIAS_RES, 1, 0><<<grid, 512, GEMM_SMEM_REQ>>>(
            ath, atl, EE, 0, woh, nullptr, EE, 0, bo, resid,
            hbuf, nullptr, nullptr, CC, 0, EE);
    }

    // 8. LayerNorm -> final output region
    ln_kernel<<<BB * TT, 128>>>(hbuf, gamma, beta, final_out);
}

// round 8
// speedup vs baseline: 1.2756x; 1.2756x over previous
#include <cuda_runtime.h>
#include <cuda_bf16.h>
#include <cstdint>

#define BB 8
#define CC 512
#define TT 2048
#define EE 512
#define LN_EPS 1e-5f

typedef __nv_bfloat16 bf16;

// ------------------------------------------------------------------
// scratch (device globals — allocation-free rule)
// ------------------------------------------------------------------
__device__ float g_resid[BB * TT * CC];
__device__ bf16  g_resid_h[BB * TT * CC];
__device__ bf16  g_resid_l[BB * TT * CC];
__device__ bf16  g_q_h[BB * TT * EE];
__device__ bf16  g_q_l[BB * TT * EE];
__device__ bf16  g_k_h[BB * TT * EE];
__device__ bf16  g_k_l[BB * TT * EE];
__device__ bf16  g_vt_h[BB * EE * TT];   // v transposed: [B][E][T]
__device__ bf16  g_vt_l[BB * EE * TT];
__device__ bf16  g_attn_h[(size_t)BB * TT * TT];
__device__ bf16  g_attn_l[(size_t)BB * TT * TT];
__device__ bf16  g_att_h[BB * TT * EE];
__device__ bf16  g_att_l[BB * TT * EE];
__device__ float g_h[BB * TT * CC];
__device__ bf16  g_WqT_h[EE * CC], g_WqT_l[EE * CC];  // [E,C] = Wq^T
__device__ bf16  g_WkT_h[EE * CC], g_WkT_l[EE * CC];
__device__ bf16  g_WvT_h[EE * CC], g_WvT_l[EE * CC];
__device__ bf16  g_WoT_h[CC * EE], g_WoT_l[CC * EE];  // [C,E] = Wo^T

// ------------------------------------------------------------------
// low-level helpers (family-portable ISA only: ldmatrix / mma.sync / cp.async)
// ------------------------------------------------------------------
__device__ __forceinline__ uint32_t smem_u32(const void* p) {
    uint32_t a;
    asm("{ .reg .u64 t; cvta.to.shared.u64 t, %1; cvt.u32.u64 %0, t; }" : "=r"(a) : "l"(p));
    return a;
}

__device__ __forceinline__ uint32_t swz64(uint32_t o) { return o ^ ((o >> 3) & 0x30); }

#define CP16(dst, src) \
    asm volatile("cp.async.cg.shared.global [%0], [%1], 16;" :: "r"(dst), "l"(src))
#define CP_COMMIT() asm volatile("cp.async.commit_group;" ::: "memory")
#define CP_WAIT(n)  asm volatile("cp.async.wait_group %0;" :: "n"(n) : "memory")

__device__ __forceinline__ void ldsm4(uint32_t* r, uint32_t addr) {
    asm volatile("ldmatrix.sync.aligned.m8n8.x4.shared.b16 {%0,%1,%2,%3}, [%4];"
                 : "=r"(r[0]), "=r"(r[1]), "=r"(r[2]), "=r"(r[3]) : "r"(addr));
}

// NOTE: intentionally NOT volatile — pure register dataflow; lets ptxas schedule.
__device__ __forceinline__ void mma_bf16(float* c, const uint32_t* a,
                                         uint32_t b0, uint32_t b1) {
    asm("mma.sync.aligned.m16n8k16.row.col.f32.bf16.bf16.f32 "
        "{%0,%1,%2,%3}, {%4,%5,%6,%7}, {%8,%9}, {%0,%1,%2,%3};"
        : "+f"(c[0]), "+f"(c[1]), "+f"(c[2]), "+f"(c[3])
        : "r"(a[0]), "r"(a[1]), "r"(a[2]), "r"(a[3]), "r"(b0), "r"(b1));
}

__device__ __forceinline__ void split2(float v, bf16& h, bf16& l) {
    h = __float2bfloat16(v);
    l = __float2bfloat16(v - __bfloat162float(h));
}

// ------------------------------------------------------------------
// HMMA GEMM: D[128m x 128n] = (Ah+Al)·(Bh+Bl)^T  (3-term split, term-interleaved)
// A row-major [M,K], B row-major [N,K]. BK=32.
// 512 threads, 16 warps as 4(m) x 4(n); warp tile 32x32.
// 3-stage cp.async pipeline, ONE barrier per chunk.
// MMA issue order: term-outer (hh all accs, hl all accs, lh all accs) so
// same-accumulator reuse distance is 8 MMAs -> per-warp ILP hides HMMA latency.
// ------------------------------------------------------------------
#define TILE_B (128 * 32 * 2)          // 8 KB per bf16 tile
#define CHUNK_B (4 * TILE_B)           // 32 KB (Ah,Al,Bh,Bl)
#define NSTAGE 3
#define GEMM_SMEM_REQ (NSTAGE * CHUNK_B)   // 96 KB (epilogue stage 66KB reuses it)

enum { EPI_F32 = 0, EPI_BIAS_SPLIT = 1, EPI_BIAS_SPLIT_T = 2, EPI_SPLIT = 3, EPI_F32_BIAS_RES = 4 };

template <int EPI>
__global__ __launch_bounds__(512)
void hmma_gemm(const bf16* __restrict__ Ah, const bf16* __restrict__ Al, int ldA, size_t sA,
               const bf16* __restrict__ Bh, const bf16* __restrict__ Bl, int ldB, size_t sB,
               const float* __restrict__ bias, const float* __restrict__ res,
               float* __restrict__ Cf, bf16* __restrict__ Ch, bf16* __restrict__ Cl,
               int ldc, size_t sC, int K) {
    extern __shared__ char sm[];
    uint32_t smu = smem_u32(sm);

    const int tid = threadIdx.x;
    const int w = tid >> 5, lane = tid & 31;
    const int bz = blockIdx.z;
    const int m0 = blockIdx.y * 128;
    const int n0 = blockIdx.x * 128;

    const bf16* pAh = Ah + (size_t)bz * sA + (size_t)m0 * ldA;
    const bf16* pAl = Al + (size_t)bz * sA + (size_t)m0 * ldA;
    const bf16* pBh = Bh + (size_t)bz * sB + (size_t)n0 * ldB;
    const bf16* pBl = Bl + (size_t)bz * sB + (size_t)n0 * ldB;

    // loader: 512 segments per tile, 4 tiles, 512 threads -> 4 cp.async each
    const int lrow = tid >> 2, lcs = tid & 3;
    const uint32_t loff = swz64((uint32_t)(lrow * 64 + lcs * 16));
    auto load_chunk = [&](int buf, int k0) {
        uint32_t base = smu + (uint32_t)buf * CHUNK_B;
        CP16(base + 0 * TILE_B + loff, pAh + (size_t)lrow * ldA + k0 + lcs * 8);
        CP16(base + 1 * TILE_B + loff, pAl + (size_t)lrow * ldA + k0 + lcs * 8);
        CP16(base + 2 * TILE_B + loff, pBh + (size_t)lrow * ldB + k0 + lcs * 8);
        CP16(base + 3 * TILE_B + loff, pBl + (size_t)lrow * ldB + k0 + lcs * 8);
    };

    // warp layout: 4 (m) x 4 (n); warp tile 32 x 32
    const int wm = w >> 2, wn = w & 3;
    const int lr = lane & 7;
    const int r8 = (lane >> 3) & 1;
    const int chi = lane >> 4;

    uint32_t offA[2][2], offB[2][2];
#pragma unroll
    for (int mt = 0; mt < 2; mt++)
#pragma unroll
        for (int ks = 0; ks < 2; ks++)
            offA[mt][ks] = swz64((uint32_t)((wm * 32 + mt * 16 + r8 * 8 + lr) * 64 + (2 * ks + chi) * 16));
#pragma unroll
    for (int nt = 0; nt < 2; nt++)
#pragma unroll
        for (int ks = 0; ks < 2; ks++)
            offB[nt][ks] = swz64((uint32_t)((wn * 32 + nt * 16 + r8 * 8 + lr) * 64 + (2 * ks + chi) * 16));

    float acc[2][4][4];   // [mt][nt*2+nh][quad]
#pragma unroll
    for (int i = 0; i < 2; i++)
#pragma unroll
        for (int j = 0; j < 4; j++)
#pragma unroll
            for (int q = 0; q < 4; q++) acc[i][j][q] = 0.f;

    const int nch = K / 32;
    load_chunk(0, 0);
    CP_COMMIT();
    if (nch > 1) load_chunk(1, 32);
    CP_COMMIT();

    int buf = 0;
    for (int c = 0; c < nch; c++) {
        CP_WAIT(1);          // group c complete (c+2 not yet committed)
        __syncthreads();     // orders prior-iter reads of buf (c+2)%3 before its overwrite

        if (c + 2 < nch) {
            int fb = buf + 2;
            if (fb >= NSTAGE) fb -= NSTAGE;
            load_chunk(fb, (c + 2) * 32);
        }
        CP_COMMIT();         // always commit (possibly empty) -> wait(1) stays exact

        uint32_t bu = smu + (uint32_t)buf * CHUNK_B;
#pragma unroll
        for (int ks = 0; ks < 2; ks++) {
            uint32_t afh[2][4], afl[2][4], bfh[2][4], bfl[2][4];
#pragma unroll
            for (int mt = 0; mt < 2; mt++) {
                ldsm4(afh[mt], bu + 0 * TILE_B + offA[mt][ks]);
                ldsm4(afl[mt], bu + 1 * TILE_B + offA[mt][ks]);
            }
#pragma unroll
            for (int nt = 0; nt < 2; nt++) {
                ldsm4(bfh[nt], bu + 2 * TILE_B + offB[nt][ks]);
                ldsm4(bfl[nt], bu + 3 * TILE_B + offB[nt][ks]);
            }
            // round 1: hh into all 8 accumulators
#pragma unroll
            for (int mt = 0; mt < 2; mt++)
#pragma unroll
                for (int nt = 0; nt < 2; nt++) {
                    mma_bf16(acc[mt][nt * 2 + 0], afh[mt], bfh[nt][0], bfh[nt][2]);
                    mma_bf16(acc[mt][nt * 2 + 1], afh[mt], bfh[nt][1], bfh[nt][3]);
                }
            // round 2: hl into all 8
#pragma unroll
            for (int mt = 0; mt < 2; mt++)
#pragma unroll
                for (int nt = 0; nt < 2; nt++) {
                    mma_bf16(acc[mt][nt * 2 + 0], afh[mt], bfl[nt][0], bfl[nt][2]);
                    mma_bf16(acc[mt][nt * 2 + 1], afh[mt], bfl[nt][1], bfl[nt][3]);
                }
            // round 3: lh into all 8
#pragma unroll
            for (int mt = 0; mt < 2; mt++)
#pragma unroll
                for (int nt = 0; nt < 2; nt++) {
                    mma_bf16(acc[mt][nt * 2 + 0], afl[mt], bfh[nt][0], bfh[nt][2]);
                    mma_bf16(acc[mt][nt * 2 + 1], afl[mt], bfh[nt][1], bfh[nt][3]);
                }
        }
        buf++;
        if (buf == NSTAGE) buf = 0;
    }
    __syncthreads();   // all compute done before st overwrites buffers

    // ---- epilogue: accumulators -> staged smem [128][129] fp32 -> gmem ----
    float* st = (float*)sm;
    {
        int g = lane >> 2, t4 = lane & 3;
#pragma unroll
        for (int mt = 0; mt < 2; mt++) {
            int r = wm * 32 + mt * 16 + g;
#pragma unroll
            for (int j = 0; j < 4; j++) {
                int ccol = wn * 32 + j * 8 + 2 * t4;
                st[r * 129 + ccol]           = acc[mt][j][0];
                st[r * 129 + ccol + 1]       = acc[mt][j][1];
                st[(r + 8) * 129 + ccol]     = acc[mt][j][2];
                st[(r + 8) * 129 + ccol + 1] = acc[mt][j][3];
            }
        }
    }
    __syncthreads();

    if (EPI == EPI_BIAS_SPLIT_T) {
        // transposed split store: dest vt[b][e][t]
#pragma unroll 4
        for (int it = 0; it < 8; it++) {
            int col = w + 16 * it;
            float bv = bias[n0 + col];
#pragma unroll
            for (int j = 0; j < 4; j++) {
                int row = lane + 32 * j;
                float v = st[row * 129 + col] + bv;
                size_t m = (size_t)m0 + row;
                int bb_ = (int)(m / TT);
                int t = (int)(m % TT);
                size_t off = ((size_t)bb_ * EE + (n0 + col)) * TT + t;
                bf16 h, l; split2(v, h, l);
                Ch[off] = h;
                Cl[off] = l;
            }
        }
    } else {
        float bv[4];
#pragma unroll
        for (int cb = 0; cb < 4; cb++)
            bv[cb] = (EPI == EPI_BIAS_SPLIT || EPI == EPI_F32_BIAS_RES) ? bias[n0 + lane + 32 * cb] : 0.f;

#pragma unroll 2
        for (int rr = 0; rr < 8; rr++) {
            int row = w * 8 + rr;
            size_t m = (size_t)m0 + row;
#pragma unroll
            for (int cb = 0; cb < 4; cb++) {
                int col = lane + 32 * cb;
                float v = st[row * 129 + col] + bv[cb];
                size_t off = (size_t)bz * sC + m * ldc + n0 + col;
                if (EPI == EPI_F32) {
                    Cf[off] = v;
                } else if (EPI == EPI_F32_BIAS_RES) {
                    Cf[off] = v + res[m * ldc + n0 + col];
                } else {  // split row-major
                    bf16 h, l; split2(v, h, l);
                    Ch[off] = h;
                    Cl[off] = l;
                }
            }
        }
    }
}

// ------------------------------------------------------------------
// transpose + split: x[B,C,T] -> resid[B,T,C] (fp32 + hi/lo bf16)
// ------------------------------------------------------------------
__global__ __launch_bounds__(256)
void transpose_split(const float* __restrict__ x, float* __restrict__ r,
                     bf16* __restrict__ rh, bf16* __restrict__ rl) {
    __shared__ float tile[32][33];
    int b = blockIdx.z;
    int t0 = blockIdx.x * 32;
    int c0 = blockIdx.y * 32;
    const float* xb = x + (size_t)b * CC * TT;
    size_t ob = (size_t)b * TT * CC;
    int tx = threadIdx.x, ty = threadIdx.y;
#pragma unroll
    for (int i = ty; i < 32; i += 8)
        tile[i][tx] = xb[(size_t)(c0 + i) * TT + t0 + tx];
    __syncthreads();
#pragma unroll
    for (int i = ty; i < 32; i += 8) {
        float v = tile[tx][i];
        size_t off = ob + (size_t)(t0 + i) * CC + c0 + tx;
        r[off] = v;
        bf16 h, l; split2(v, h, l);
        rh[off] = h;
        rl[off] = l;
    }
}

// W [512,512] -> W^T hi/lo [512,512]
__global__ __launch_bounds__(256)
void wsplit(const float* __restrict__ W, bf16* __restrict__ Th, bf16* __restrict__ Tl) {
    __shared__ float tile[32][33];
    int k0 = blockIdx.y * 32, n0 = blockIdx.x * 32;
    int tx = threadIdx.x, ty = threadIdx.y;
#pragma unroll
    for (int i = ty; i < 32; i += 8)
        tile[i][tx] = W[(size_t)(k0 + i) * 512 + n0 + tx];
    __syncthreads();
#pragma unroll
    for (int i = ty; i < 32; i += 8) {
        float v = tile[tx][i];  // W[k0+tx][n0+i]
        size_t off = (size_t)(n0 + i) * 512 + k0 + tx;
        bf16 h, l; split2(v, h, l);
        Th[off] = h;
        Tl[off] = l;
    }
}

// ------------------------------------------------------------------
// softmax (in-place fp32) + emit hi/lo bf16
// ------------------------------------------------------------------
__global__ __launch_bounds__(256)
void softmax_split(float* __restrict__ attn, bf16* __restrict__ ah, bf16* __restrict__ al) {
    size_t ro = (size_t)blockIdx.x * TT;
    float* row = attn + ro;
    int t = threadIdx.x;
    float vals[8];
    float m = -1e30f;
#pragma unroll
    for (int j = 0; j < 8; j++) {
        vals[j] = row[t + 256 * j];
        m = fmaxf(m, vals[j]);
    }
#pragma unroll
    for (int o = 16; o; o >>= 1) m = fmaxf(m, __shfl_xor_sync(0xffffffffu, m, o));
    __shared__ float smax[8], ssum[8];
    if ((t & 31) == 0) smax[t >> 5] = m;
    __syncthreads();
    float rm = smax[0];
#pragma unroll
    for (int i = 1; i < 8; i++) rm = fmaxf(rm, smax[i]);

    float s = 0.f;
#pragma unroll
    for (int j = 0; j < 8; j++) {
        vals[j] = expf(vals[j] - rm);
        s += vals[j];
    }
#pragma unroll
    for (int o = 16; o; o >>= 1) s += __shfl_xor_sync(0xffffffffu, s, o);
    if ((t & 31) == 0) ssum[t >> 5] = s;
    __syncthreads();
    float tot = 0.f;
#pragma unroll
    for (int i = 0; i < 8; i++) tot += ssum[i];
    float inv = 1.f / tot;

#pragma unroll
    for (int j = 0; j < 8; j++) {
        float v = vals[j] * inv;
        row[t + 256 * j] = v;
        bf16 h, l; split2(v, h, l);
        ah[ro + t + 256 * j] = h;
        al[ro + t + 256 * j] = l;
    }
}

// ------------------------------------------------------------------
// LayerNorm over C=512
// ------------------------------------------------------------------
__global__ __launch_bounds__(128)
void ln_kernel(const float* __restrict__ h, const float* __restrict__ gamma,
               const float* __restrict__ beta, float* __restrict__ out) {
    const float* hr = h + (size_t)blockIdx.x * CC;
    int t = threadIdx.x;
    float4 v = ((const float4*)hr)[t];

    float s = v.x + v.y + v.z + v.w;
#pragma unroll
    for (int o = 16; o; o >>= 1) s += __shfl_xor_sync(0xffffffffu, s, o);
    __shared__ float s1[4], s2[4];
    if ((t & 31) == 0) s1[t >> 5] = s;
    __syncthreads();
    float mu = (s1[0] + s1[1] + s1[2] + s1[3]) * (1.f / CC);

    float dx = v.x - mu, dy = v.y - mu, dz = v.z - mu, dw = v.w - mu;
    float q = dx * dx + dy * dy + dz * dz + dw * dw;
#pragma unroll
    for (int o = 16; o; o >>= 1) q += __shfl_xor_sync(0xffffffffu, q, o);
    if ((t & 31) == 0) s2[t >> 5] = q;
    __syncthreads();
    float var = (s2[0] + s2[1] + s2[2] + s2[3]) * (1.f / CC);
    float inv = rsqrtf(var + LN_EPS);

    float4 g = ((const float4*)gamma)[t];
    float4 b = ((const float4*)beta)[t];
    float4 o4;
    o4.x = dx * inv * g.x + b.x;
    o4.y = dy * inv * g.y + b.y;
    o4.z = dz * inv * g.z + b.z;
    o4.w = dw * inv * g.w + b.w;
    ((float4*)(out + (size_t)blockIdx.x * CC))[t] = o4;
}

// ------------------------------------------------------------------
// launch
// ------------------------------------------------------------------
extern "C" void kernel_launch(void* const* d_in, const int* in_sizes, int n_in,
                              void* d_out, int out_size) {
    const float* x     = (const float*)d_in[0];
    const float* Wq    = (const float*)d_in[1];
    const float* bq    = (const float*)d_in[2];
    const float* Wk    = (const float*)d_in[3];
    const float* bk    = (const float*)d_in[4];
    const float* Wv    = (const float*)d_in[5];
    const float* bv    = (const float*)d_in[6];
    const float* Wo    = (const float*)d_in[7];
    const float* bo    = (const float*)d_in[8];
    const float* gamma = (const float*)d_in[9];
    const float* beta  = (const float*)d_in[10];

    float* out = (float*)d_out;
    float* attn = out;
    float* final_out = out + (size_t)BB * TT * TT;

    float *resid, *hbuf;
    bf16 *rh, *rl, *qh, *ql, *kh, *kl, *vth, *vtl, *anh, *anl, *ath, *atl;
    bf16 *wqh, *wql, *wkh, *wkl, *wvh, *wvl, *woh, *wol;
    cudaGetSymbolAddress((void**)&resid, g_resid);
    cudaGetSymbolAddress((void**)&hbuf, g_h);
    cudaGetSymbolAddress((void**)&rh, g_resid_h);
    cudaGetSymbolAddress((void**)&rl, g_resid_l);
    cudaGetSymbolAddress((void**)&qh, g_q_h);
    cudaGetSymbolAddress((void**)&ql, g_q_l);
    cudaGetSymbolAddress((void**)&kh, g_k_h);
    cudaGetSymbolAddress((void**)&kl, g_k_l);
    cudaGetSymbolAddress((void**)&vth, g_vt_h);
    cudaGetSymbolAddress((void**)&vtl, g_vt_l);
    cudaGetSymbolAddress((void**)&anh, g_attn_h);
    cudaGetSymbolAddress((void**)&anl, g_attn_l);
    cudaGetSymbolAddress((void**)&ath, g_att_h);
    cudaGetSymbolAddress((void**)&atl, g_att_l);
    cudaGetSymbolAddress((void**)&wqh, g_WqT_h);
    cudaGetSymbolAddress((void**)&wql, g_WqT_l);
    cudaGetSymbolAddress((void**)&wkh, g_WkT_h);
    cudaGetSymbolAddress((void**)&wkl, g_WkT_l);
    cudaGetSymbolAddress((void**)&wvh, g_WvT_h);
    cudaGetSymbolAddress((void**)&wvl, g_WvT_l);
    cudaGetSymbolAddress((void**)&woh, g_WoT_h);
    cudaGetSymbolAddress((void**)&wol, g_WoT_l);

    cudaFuncSetAttribute(hmma_gemm<EPI_F32>,          cudaFuncAttributeMaxDynamicSharedMemorySize, GEMM_SMEM_REQ);
    cudaFuncSetAttribute(hmma_gemm<EPI_BIAS_SPLIT>,   cudaFuncAttributeMaxDynamicSharedMemorySize, GEMM_SMEM_REQ);
    cudaFuncSetAttribute(hmma_gemm<EPI_BIAS_SPLIT_T>, cudaFuncAttributeMaxDynamicSharedMemorySize, GEMM_SMEM_REQ);
    cudaFuncSetAttribute(hmma_gemm<EPI_SPLIT>,        cudaFuncAttributeMaxDynamicSharedMemorySize, GEMM_SMEM_REQ);
    cudaFuncSetAttribute(hmma_gemm<EPI_F32_BIAS_RES>, cudaFuncAttributeMaxDynamicSharedMemorySize, GEMM_SMEM_REQ);

    // 1. transpose + split
    transpose_split<<<dim3(TT / 32, CC / 32, BB), dim3(32, 8)>>>(x, resid, rh, rl);

    // 2. weight transpose + split (tiny)
    wsplit<<<dim3(16, 16), dim3(32, 8)>>>(Wq, wqh, wql);
    wsplit<<<dim3(16, 16), dim3(32, 8)>>>(Wk, wkh, wkl);
    wsplit<<<dim3(16, 16), dim3(32, 8)>>>(Wv, wvh, wvl);
    wsplit<<<dim3(16, 16), dim3(32, 8)>>>(Wo, woh, wol);

    // 3. QKV projections: [16384,512] x [512,512]^T (stored [E,C])
    {
        dim3 grid(EE / 128, (BB * TT) / 128, 1);
        hmma_gemm<EPI_BIAS_SPLIT><<<grid, 512, GEMM_SMEM_REQ>>>(
            rh, rl, CC, 0, wqh, wql, CC, 0, bq, nullptr,
            nullptr, qh, ql, EE, 0, CC);
        hmma_gemm<EPI_BIAS_SPLIT><<<grid, 512, GEMM_SMEM_REQ>>>(
            rh, rl, CC, 0, wkh, wkl, CC, 0, bk, nullptr,
            nullptr, kh, kl, EE, 0, CC);
        hmma_gemm<EPI_BIAS_SPLIT_T><<<grid, 512, GEMM_SMEM_REQ>>>(
            rh, rl, CC, 0, wvh, wvl, CC, 0, bv, nullptr,
            nullptr, vth, vtl, EE, 0, CC);
    }

    // 4. energy = q @ k^T -> fp32 logits in attn output region
    {
        dim3 grid(TT / 128, TT / 128, BB);
        hmma_gemm<EPI_F32><<<grid, 512, GEMM_SMEM_REQ>>>(
            qh, ql, EE, (size_t)TT * EE, kh, kl, EE, (size_t)TT * EE,
            nullptr, nullptr, attn, nullptr, nullptr, TT, (size_t)TT * TT, EE);
    }

    // 5. softmax in-place + split
    softmax_split<<<BB * TT, 256>>>(attn, anh, anl);

    // 6. attended = attn @ v   (B operand = v^T [E,T])
    {
        dim3 grid(EE / 128, TT / 128, BB);
        hmma_gemm<EPI_SPLIT><<<grid, 512, GEMM_SMEM_REQ>>>(
            anh, anl, TT, (size_t)TT * TT, vth, vtl, TT, (size_t)EE * TT,
            nullptr, nullptr, nullptr, ath, atl, EE, (size_t)TT * EE, TT);
    }

    // 7. h = attended @ Wo + bo + resid (fp32)
    {
        dim3 grid(CC / 128, (BB * TT) / 128, 1);
        hmma_gemm<EPI_F32_BIAS_RES><<<grid, 512, GEMM_SMEM_REQ>>>(
            ath, atl, EE, 0, woh, wol, EE, 0, bo, resid,
            hbuf, nullptr, nullptr, CC, 0, EE);
    }

    // 8. LayerNorm -> final output region
    ln_kernel<<<BB * TT, 128>>>(hbuf, gamma, beta, final_out);
}

// round 9
// speedup vs baseline: 1.4983x; 1.1746x over previous
#include <cuda_runtime.h>
#include <cuda_bf16.h>
#include <cstdint>

#define BB 8
#define CC 512
#define TT 2048
#define EE 512
#define LN_EPS 1e-5f

typedef __nv_bfloat16 bf16;

// ------------------------------------------------------------------
// scratch (device globals — allocation-free rule)
// ------------------------------------------------------------------
__device__ float g_resid[BB * TT * CC];
__device__ bf16  g_resid_h[BB * TT * CC];
__device__ bf16  g_resid_l[BB * TT * CC];
__device__ bf16  g_q_h[BB * TT * EE];
__device__ bf16  g_q_l[BB * TT * EE];
__device__ bf16  g_k_h[BB * TT * EE];
__device__ bf16  g_k_l[BB * TT * EE];
__device__ bf16  g_vt_h[BB * EE * TT];   // v transposed: [B][E][T]
__device__ bf16  g_vt_l[BB * EE * TT];
__device__ bf16  g_attn_h[(size_t)BB * TT * TT];
__device__ bf16  g_att_h[BB * TT * EE];
__device__ bf16  g_att_l[BB * TT * EE];
__device__ float g_h[BB * TT * CC];
__device__ bf16  g_WqT_h[EE * CC], g_WqT_l[EE * CC];  // [E,C] = Wq^T
__device__ bf16  g_WkT_h[EE * CC], g_WkT_l[EE * CC];
__device__ bf16  g_WvT_h[EE * CC], g_WvT_l[EE * CC];
__device__ bf16  g_WoT_h[CC * EE], g_WoT_l[CC * EE];  // [C,E] = Wo^T

// ------------------------------------------------------------------
// low-level helpers (family-portable ISA only: ldmatrix / mma.sync / cp.async)
// ------------------------------------------------------------------
__device__ __forceinline__ uint32_t smem_u32(const void* p) {
    uint32_t a;
    asm("{ .reg .u64 t; cvta.to.shared.u64 t, %1; cvt.u32.u64 %0, t; }" : "=r"(a) : "l"(p));
    return a;
}

__device__ __forceinline__ uint32_t swz64(uint32_t o) { return o ^ ((o >> 3) & 0x30); }

#define CP16(dst, src) \
    asm volatile("cp.async.cg.shared.global [%0], [%1], 16;" :: "r"(dst), "l"(src))
#define CP_COMMIT() asm volatile("cp.async.commit_group;" ::: "memory")
#define CP_WAIT(n)  asm volatile("cp.async.wait_group %0;" :: "n"(n) : "memory")

__device__ __forceinline__ void ldsm4(uint32_t* r, uint32_t addr) {
    asm volatile("ldmatrix.sync.aligned.m8n8.x4.shared.b16 {%0,%1,%2,%3}, [%4];"
                 : "=r"(r[0]), "=r"(r[1]), "=r"(r[2]), "=r"(r[3]) : "r"(addr));
}

// NOT volatile — pure register dataflow; lets ptxas schedule.
__device__ __forceinline__ void mma_bf16(float* c, const uint32_t* a,
                                         uint32_t b0, uint32_t b1) {
    asm("mma.sync.aligned.m16n8k16.row.col.f32.bf16.bf16.f32 "
        "{%0,%1,%2,%3}, {%4,%5,%6,%7}, {%8,%9}, {%0,%1,%2,%3};"
        : "+f"(c[0]), "+f"(c[1]), "+f"(c[2]), "+f"(c[3])
        : "r"(a[0]), "r"(a[1]), "r"(a[2]), "r"(a[3]), "r"(b0), "r"(b1));
}

__device__ __forceinline__ void split2(float v, bf16& h, bf16& l) {
    h = __float2bfloat16(v);
    l = __float2bfloat16(v - __bfloat162float(h));
}

// ------------------------------------------------------------------
// HMMA GEMM: D[128m x 128n] = selected terms of (Ah+Al)·(Bh+Bl)^T
// Terms: AhBh always; + AhBl if USE_BL; + AlBh if USE_AL.
// A row-major [M,K], B row-major [N,K]. BK=32.
// 512 threads, 16 warps as 4(m) x 4(n); warp tile 32x32.
// 3-stage cp.async pipeline, ONE barrier per chunk; term-outer MMA order.
// ------------------------------------------------------------------
#define TILE_B (128 * 32 * 2)          // 8 KB per bf16 tile
#define CHUNK_B (4 * TILE_B)           // 32 KB slots (Ah,Al,Bh,Bl; unused not loaded)
#define NSTAGE 3
#define GEMM_SMEM_REQ (NSTAGE * CHUNK_B)   // 96 KB (epilogue stage 66KB reuses it)

enum { EPI_F32 = 0, EPI_BIAS_SPLIT = 1, EPI_BIAS_SPLIT_T = 2, EPI_SPLIT = 3, EPI_F32_BIAS_RES = 4 };

template <int EPI, int USE_AL, int USE_BL>
__global__ __launch_bounds__(512)
void hmma_gemm(const bf16* __restrict__ Ah, const bf16* __restrict__ Al, int ldA, size_t sA,
               const bf16* __restrict__ Bh, const bf16* __restrict__ Bl, int ldB, size_t sB,
               const float* __restrict__ bias, const float* __restrict__ res,
               float* __restrict__ Cf, bf16* __restrict__ Ch, bf16* __restrict__ Cl,
               int ldc, size_t sC, int K) {
    extern __shared__ char sm[];
    uint32_t smu = smem_u32(sm);

    const int tid = threadIdx.x;
    const int w = tid >> 5, lane = tid & 31;
    const int bz = blockIdx.z;
    const int m0 = blockIdx.y * 128;
    const int n0 = blockIdx.x * 128;

    const bf16* pAh = Ah + (size_t)bz * sA + (size_t)m0 * ldA;
    const bf16* pAl = USE_AL ? (Al + (size_t)bz * sA + (size_t)m0 * ldA) : nullptr;
    const bf16* pBh = Bh + (size_t)bz * sB + (size_t)n0 * ldB;
    const bf16* pBl = USE_BL ? (Bl + (size_t)bz * sB + (size_t)n0 * ldB) : nullptr;

    const int lrow = tid >> 2, lcs = tid & 3;
    const uint32_t loff = swz64((uint32_t)(lrow * 64 + lcs * 16));
    auto load_chunk = [&](int buf, int k0) {
        uint32_t base = smu + (uint32_t)buf * CHUNK_B;
        CP16(base + 0 * TILE_B + loff, pAh + (size_t)lrow * ldA + k0 + lcs * 8);
        if (USE_AL) CP16(base + 1 * TILE_B + loff, pAl + (size_t)lrow * ldA + k0 + lcs * 8);
        CP16(base + 2 * TILE_B + loff, pBh + (size_t)lrow * ldB + k0 + lcs * 8);
        if (USE_BL) CP16(base + 3 * TILE_B + loff, pBl + (size_t)lrow * ldB + k0 + lcs * 8);
    };

    // warp layout: 4 (m) x 4 (n); warp tile 32 x 32
    const int wm = w >> 2, wn = w & 3;
    const int lr = lane & 7;
    const int r8 = (lane >> 3) & 1;
    const int chi = lane >> 4;

    uint32_t offA[2][2], offB[2][2];
#pragma unroll
    for (int mt = 0; mt < 2; mt++)
#pragma unroll
        for (int ks = 0; ks < 2; ks++)
            offA[mt][ks] = swz64((uint32_t)((wm * 32 + mt * 16 + r8 * 8 + lr) * 64 + (2 * ks + chi) * 16));
#pragma unroll
    for (int nt = 0; nt < 2; nt++)
#pragma unroll
        for (int ks = 0; ks < 2; ks++)
            offB[nt][ks] = swz64((uint32_t)((wn * 32 + nt * 16 + r8 * 8 + lr) * 64 + (2 * ks + chi) * 16));

    float acc[2][4][4];
#pragma unroll
    for (int i = 0; i < 2; i++)
#pragma unroll
        for (int j = 0; j < 4; j++)
#pragma unroll
            for (int q = 0; q < 4; q++) acc[i][j][q] = 0.f;

    const int nch = K / 32;
    load_chunk(0, 0);
    CP_COMMIT();
    if (nch > 1) load_chunk(1, 32);
    CP_COMMIT();

    int buf = 0;
    for (int c = 0; c < nch; c++) {
        CP_WAIT(1);
        __syncthreads();

        if (c + 2 < nch) {
            int fb = buf + 2;
            if (fb >= NSTAGE) fb -= NSTAGE;
            load_chunk(fb, (c + 2) * 32);
        }
        CP_COMMIT();

        uint32_t bu = smu + (uint32_t)buf * CHUNK_B;
#pragma unroll
        for (int ks = 0; ks < 2; ks++) {
            uint32_t afh[2][4], afl[2][4], bfh[2][4], bfl[2][4];
#pragma unroll
            for (int mt = 0; mt < 2; mt++) {
                ldsm4(afh[mt], bu + 0 * TILE_B + offA[mt][ks]);
                if (USE_AL) ldsm4(afl[mt], bu + 1 * TILE_B + offA[mt][ks]);
            }
#pragma unroll
            for (int nt = 0; nt < 2; nt++) {
                ldsm4(bfh[nt], bu + 2 * TILE_B + offB[nt][ks]);
                if (USE_BL) ldsm4(bfl[nt], bu + 3 * TILE_B + offB[nt][ks]);
            }
            // round 1: hh into all 8 accumulators
#pragma unroll
            for (int mt = 0; mt < 2; mt++)
#pragma unroll
                for (int nt = 0; nt < 2; nt++) {
                    mma_bf16(acc[mt][nt * 2 + 0], afh[mt], bfh[nt][0], bfh[nt][2]);
                    mma_bf16(acc[mt][nt * 2 + 1], afh[mt], bfh[nt][1], bfh[nt][3]);
                }
            // round 2: hl
            if (USE_BL) {
#pragma unroll
                for (int mt = 0; mt < 2; mt++)
#pragma unroll
                    for (int nt = 0; nt < 2; nt++) {
                        mma_bf16(acc[mt][nt * 2 + 0], afh[mt], bfl[nt][0], bfl[nt][2]);
                        mma_bf16(acc[mt][nt * 2 + 1], afh[mt], bfl[nt][1], bfl[nt][3]);
                    }
            }
            // round 3: lh
            if (USE_AL) {
#pragma unroll
                for (int mt = 0; mt < 2; mt++)
#pragma unroll
                    for (int nt = 0; nt < 2; nt++) {
                        mma_bf16(acc[mt][nt * 2 + 0], afl[mt], bfh[nt][0], bfh[nt][2]);
                        mma_bf16(acc[mt][nt * 2 + 1], afl[mt], bfh[nt][1], bfh[nt][3]);
                    }
            }
        }
        buf++;
        if (buf == NSTAGE) buf = 0;
    }
    __syncthreads();

    // ---- epilogue: accumulators -> staged smem [128][129] fp32 -> gmem ----
    float* st = (float*)sm;
    {
        int g = lane >> 2, t4 = lane & 3;
#pragma unroll
        for (int mt = 0; mt < 2; mt++) {
            int r = wm * 32 + mt * 16 + g;
#pragma unroll
            for (int j = 0; j < 4; j++) {
                int ccol = wn * 32 + j * 8 + 2 * t4;
                st[r * 129 + ccol]           = acc[mt][j][0];
                st[r * 129 + ccol + 1]       = acc[mt][j][1];
                st[(r + 8) * 129 + ccol]     = acc[mt][j][2];
                st[(r + 8) * 129 + ccol + 1] = acc[mt][j][3];
            }
        }
    }
    __syncthreads();

    if (EPI == EPI_BIAS_SPLIT_T) {
        // transposed split store: dest vt[b][e][t]
#pragma unroll 4
        for (int it = 0; it < 8; it++) {
            int col = w + 16 * it;
            float bv = bias[n0 + col];
#pragma unroll
            for (int j = 0; j < 4; j++) {
                int row = lane + 32 * j;
                float v = st[row * 129 + col] + bv;
                size_t m = (size_t)m0 + row;
                int bb_ = (int)(m / TT);
                int t = (int)(m % TT);
                size_t off = ((size_t)bb_ * EE + (n0 + col)) * TT + t;
                bf16 h, l; split2(v, h, l);
                Ch[off] = h;
                Cl[off] = l;
            }
        }
    } else {
        float bv[4];
#pragma unroll
        for (int cb = 0; cb < 4; cb++)
            bv[cb] = (EPI == EPI_BIAS_SPLIT || EPI == EPI_F32_BIAS_RES) ? bias[n0 + lane + 32 * cb] : 0.f;

#pragma unroll 2
        for (int rr = 0; rr < 8; rr++) {
            int row = w * 8 + rr;
            size_t m = (size_t)m0 + row;
#pragma unroll
            for (int cb = 0; cb < 4; cb++) {
                int col = lane + 32 * cb;
                float v = st[row * 129 + col] + bv[cb];
                size_t off = (size_t)bz * sC + m * ldc + n0 + col;
                if (EPI == EPI_F32) {
                    Cf[off] = v;
                } else if (EPI == EPI_F32_BIAS_RES) {
                    Cf[off] = v + res[m * ldc + n0 + col];
                } else {
                    bf16 h, l; split2(v, h, l);
                    Ch[off] = h;
                    Cl[off] = l;
                }
            }
        }
    }
}

// ------------------------------------------------------------------
// transpose + split: x[B,C,T] -> resid[B,T,C] (fp32 + hi/lo bf16)
// ------------------------------------------------------------------
__global__ __launch_bounds__(256)
void transpose_split(const float* __restrict__ x, float* __restrict__ r,
                     bf16* __restrict__ rh, bf16* __restrict__ rl) {
    __shared__ float tile[32][33];
    int b = blockIdx.z;
    int t0 = blockIdx.x * 32;
    int c0 = blockIdx.y * 32;
    const float* xb = x + (size_t)b * CC * TT;
    size_t ob = (size_t)b * TT * CC;
    int tx = threadIdx.x, ty = threadIdx.y;
#pragma unroll
    for (int i = ty; i < 32; i += 8)
        tile[i][tx] = xb[(size_t)(c0 + i) * TT + t0 + tx];
    __syncthreads();
#pragma unroll
    for (int i = ty; i < 32; i += 8) {
        float v = tile[tx][i];
        size_t off = ob + (size_t)(t0 + i) * CC + c0 + tx;
        r[off] = v;
        bf16 h, l; split2(v, h, l);
        rh[off] = h;
        rl[off] = l;
    }
}

// W [512,512] -> W^T hi/lo [512,512]
__global__ __launch_bounds__(256)
void wsplit(const float* __restrict__ W, bf16* __restrict__ Th, bf16* __restrict__ Tl) {
    __shared__ float tile[32][33];
    int k0 = blockIdx.y * 32, n0 = blockIdx.x * 32;
    int tx = threadIdx.x, ty = threadIdx.y;
#pragma unroll
    for (int i = ty; i < 32; i += 8)
        tile[i][tx] = W[(size_t)(k0 + i) * 512 + n0 + tx];
    __syncthreads();
#pragma unroll
    for (int i = ty; i < 32; i += 8) {
        float v = tile[tx][i];
        size_t off = (size_t)(n0 + i) * 512 + k0 + tx;
        bf16 h, l; split2(v, h, l);
        Th[off] = h;
        Tl[off] = l;
    }
}

// ------------------------------------------------------------------
// softmax (in-place fp32) + emit hi bf16 only
// ------------------------------------------------------------------
__global__ __launch_bounds__(256)
void softmax_split(float* __restrict__ attn, bf16* __restrict__ ah) {
    size_t ro = (size_t)blockIdx.x * TT;
    float* row = attn + ro;
    int t = threadIdx.x;
    float vals[8];
    float m = -1e30f;
#pragma unroll
    for (int j = 0; j < 8; j++) {
        vals[j] = row[t + 256 * j];
        m = fmaxf(m, vals[j]);
    }
#pragma unroll
    for (int o = 16; o; o >>= 1) m = fmaxf(m, __shfl_xor_sync(0xffffffffu, m, o));
    __shared__ float smax[8], ssum[8];
    if ((t & 31) == 0) smax[t >> 5] = m;
    __syncthreads();
    float rm = smax[0];
#pragma unroll
    for (int i = 1; i < 8; i++) rm = fmaxf(rm, smax[i]);

    float s = 0.f;
#pragma unroll
    for (int j = 0; j < 8; j++) {
        vals[j] = expf(vals[j] - rm);
        s += vals[j];
    }
#pragma unroll
    for (int o = 16; o; o >>= 1) s += __shfl_xor_sync(0xffffffffu, s, o);
    if ((t & 31) == 0) ssum[t >> 5] = s;
    __syncthreads();
    float tot = 0.f;
#pragma unroll
    for (int i = 0; i < 8; i++) tot += ssum[i];
    float inv = 1.f / tot;

#pragma unroll
    for (int j = 0; j < 8; j++) {
        float v = vals[j] * inv;
        row[t + 256 * j] = v;
        ah[ro + t + 256 * j] = __float2bfloat16(v);
    }
}

// ------------------------------------------------------------------
// LayerNorm over C=512
// ------------------------------------------------------------------
__global__ __launch_bounds__(128)
void ln_kernel(const float* __restrict__ h, const float* __restrict__ gamma,
               const float* __restrict__ beta, float* __restrict__ out) {
    const float* hr = h + (size_t)blockIdx.x * CC;
    int t = threadIdx.x;
    float4 v = ((const float4*)hr)[t];

    float s = v.x + v.y + v.z + v.w;
#pragma unroll
    for (int o = 16; o; o >>= 1) s += __shfl_xor_sync(0xffffffffu, s, o);
    __shared__ float s1[4], s2[4];
    if ((t & 31) == 0) s1[t >> 5] = s;
    __syncthreads();
    float mu = (s1[0] + s1[1] + s1[2] + s1[3]) * (1.f / CC);

    float dx = v.x - mu, dy = v.y - mu, dz = v.z - mu, dw = v.w - mu;
    float q = dx * dx + dy * dy + dz * dz + dw * dw;
#pragma unroll
    for (int o = 16; o; o >>= 1) q += __shfl_xor_sync(0xffffffffu, q, o);
    if ((t & 31) == 0) s2[t >> 5] = q;
    __syncthreads();
    float var = (s2[0] + s2[1] + s2[2] + s2[3]) * (1.f / CC);
    float inv = rsqrtf(var + LN_EPS);

    float4 g = ((const float4*)gamma)[t];
    float4 b = ((const float4*)beta)[t];
    float4 o4;
    o4.x = dx * inv * g.x + b.x;
    o4.y = dy * inv * g.y + b.y;
    o4.z = dz * inv * g.z + b.z;
    o4.w = dw * inv * g.w + b.w;
    ((float4*)(out + (size_t)blockIdx.x * CC))[t] = o4;
}

// ------------------------------------------------------------------
// launch — ordered so ncu (-s 5) lands on a QKV GEMM
// ------------------------------------------------------------------
extern "C" void kernel_launch(void* const* d_in, const int* in_sizes, int n_in,
                              void* d_out, int out_size) {
    const float* x     = (const float*)d_in[0];
    const float* Wq    = (const float*)d_in[1];
    const float* bq    = (const float*)d_in[2];
    const float* Wk    = (const float*)d_in[3];
    const float* bk    = (const float*)d_in[4];
    const float* Wv    = (const float*)d_in[5];
    const float* bv    = (const float*)d_in[6];
    const float* Wo    = (const float*)d_in[7];
    const float* bo    = (const float*)d_in[8];
    const float* gamma = (const float*)d_in[9];
    const float* beta  = (const float*)d_in[10];

    float* out = (float*)d_out;
    float* attn = out;
    float* final_out = out + (size_t)BB * TT * TT;

    float *resid, *hbuf;
    bf16 *rh, *rl, *qh, *ql, *kh, *kl, *vth, *vtl, *anh, *ath, *atl;
    bf16 *wqh, *wql, *wkh, *wkl, *wvh, *wvl, *woh, *wol;
    cudaGetSymbolAddress((void**)&resid, g_resid);
    cudaGetSymbolAddress((void**)&hbuf, g_h);
    cudaGetSymbolAddress((void**)&rh, g_resid_h);
    cudaGetSymbolAddress((void**)&rl, g_resid_l);
    cudaGetSymbolAddress((void**)&qh, g_q_h);
    cudaGetSymbolAddress((void**)&ql, g_q_l);
    cudaGetSymbolAddress((void**)&kh, g_k_h);
    cudaGetSymbolAddress((void**)&kl, g_k_l);
    cudaGetSymbolAddress((void**)&vth, g_vt_h);
    cudaGetSymbolAddress((void**)&vtl, g_vt_l);
    cudaGetSymbolAddress((void**)&anh, g_attn_h);
    cudaGetSymbolAddress((void**)&ath, g_att_h);
    cudaGetSymbolAddress((void**)&atl, g_att_l);
    cudaGetSymbolAddress((void**)&wqh, g_WqT_h);
    cudaGetSymbolAddress((void**)&wql, g_WqT_l);
    cudaGetSymbolAddress((void**)&wkh, g_WkT_h);
    cudaGetSymbolAddress((void**)&wkl, g_WkT_l);
    cudaGetSymbolAddress((void**)&wvh, g_WvT_h);
    cudaGetSymbolAddress((void**)&wvl, g_WvT_l);
    cudaGetSymbolAddress((void**)&woh, g_WoT_h);
    cudaGetSymbolAddress((void**)&wol, g_WoT_l);

    cudaFuncSetAttribute(hmma_gemm<EPI_BIAS_SPLIT, 1, 1>,   cudaFuncAttributeMaxDynamicSharedMemorySize, GEMM_SMEM_REQ);
    cudaFuncSetAttribute(hmma_gemm<EPI_BIAS_SPLIT_T, 0, 1>, cudaFuncAttributeMaxDynamicSharedMemorySize, GEMM_SMEM_REQ);
    cudaFuncSetAttribute(hmma_gemm<EPI_F32, 1, 1>,          cudaFuncAttributeMaxDynamicSharedMemorySize, GEMM_SMEM_REQ);
    cudaFuncSetAttribute(hmma_gemm<EPI_SPLIT, 0, 1>,        cudaFuncAttributeMaxDynamicSharedMemorySize, GEMM_SMEM_REQ);
    cudaFuncSetAttribute(hmma_gemm<EPI_F32_BIAS_RES, 1, 0>, cudaFuncAttributeMaxDynamicSharedMemorySize, GEMM_SMEM_REQ);

    // launches 0-4: transpose + 3 wsplits, so launch #5-ish = QKV GEMM under ncu
    transpose_split<<<dim3(TT / 32, CC / 32, BB), dim3(32, 8)>>>(x, resid, rh, rl);
    wsplit<<<dim3(16, 16), dim3(32, 8)>>>(Wq, wqh, wql);
    wsplit<<<dim3(16, 16), dim3(32, 8)>>>(Wk, wkh, wkl);
    wsplit<<<dim3(16, 16), dim3(32, 8)>>>(Wv, wvh, wvl);

    // QKV projections
    {
        dim3 grid(EE / 128, (BB * TT) / 128, 1);
        // q, k: full 3-term (logit path needs 16-bit operands)
        hmma_gemm<EPI_BIAS_SPLIT, 1, 1><<<grid, 512, GEMM_SMEM_REQ>>>(
            rh, rl, CC, 0, wqh, wql, CC, 0, bq, nullptr,
            nullptr, qh, ql, EE, 0, CC);
        hmma_gemm<EPI_BIAS_SPLIT, 1, 1><<<grid, 512, GEMM_SMEM_REQ>>>(
            rh, rl, CC, 0, wkh, wkl, CC, 0, bk, nullptr,
            nullptr, kh, kl, EE, 0, CC);
        // v: 2-term (drop resid_lo term)
        hmma_gemm<EPI_BIAS_SPLIT_T, 0, 1><<<grid, 512, GEMM_SMEM_REQ>>>(
            rh, nullptr, CC, 0, wvh, wvl, CC, 0, bv, nullptr,
            nullptr, vth, vtl, EE, 0, CC);
    }

    // Wo split (deferred; only needed before O-proj)
    wsplit<<<dim3(16, 16), dim3(32, 8)>>>(Wo, woh, wol);

    // energy = q @ k^T (full 3-term) -> fp32 logits in attn output region
    {
        dim3 grid(TT / 128, TT / 128, BB);
        hmma_gemm<EPI_F32, 1, 1><<<grid, 512, GEMM_SMEM_REQ>>>(
            qh, ql, EE, (size_t)TT * EE, kh, kl, EE, (size_t)TT * EE,
            nullptr, nullptr, attn, nullptr, nullptr, TT, (size_t)TT * TT, EE);
    }

    // softmax in-place + emit hi only
    softmax_split<<<BB * TT, 256>>>(attn, anh);

    // attended = attn_hi @ (v_hi + v_lo)  (2-term)
    {
        dim3 grid(EE / 128, TT / 128, BB);
        hmma_gemm<EPI_SPLIT, 0, 1><<<grid, 512, GEMM_SMEM_REQ>>>(
            anh, nullptr, TT, (size_t)TT * TT, vth, vtl, TT, (size_t)EE * TT,
            nullptr, nullptr, nullptr, ath, atl, EE, (size_t)TT * EE, TT);
    }

    // h = (att_hi + att_lo) @ Wo_hi + bo + resid (2-term)
    {
        dim3 grid(CC / 128, (BB * TT) / 128, 1);
        hmma_gemm<EPI_F32_BIAS_RES, 1, 0><<<grid, 512, GEMM_SMEM_REQ>>>(
            ath, atl, EE, 0, woh, nullptr, EE, 0, bo, resid,
            hbuf, nullptr, nullptr, CC, 0, EE);
    }

    // LayerNorm -> final output region
    ln_kernel<<<BB * TT, 128>>>(hbuf, gamma, beta, final_out);
}

// round 10
// speedup vs baseline: 1.5916x; 1.0623x over previous
#include <cuda_runtime.h>
#include <cuda_bf16.h>
#include <cstdint>

#define BB 8
#define CC 512
#define TT 2048
#define EE 512
#define LN_EPS 1e-5f

typedef __nv_bfloat16 bf16;

// ------------------------------------------------------------------
// scratch (device globals — allocation-free rule)
// ------------------------------------------------------------------
__device__ float g_resid[BB * TT * CC];
__device__ bf16  g_resid_h[BB * TT * CC];
__device__ bf16  g_resid_l[BB * TT * CC];
__device__ bf16  g_qm_h[BB * TT * CC];     // qm = resid @ M
__device__ bf16  g_qm_l[BB * TT * CC];
__device__ bf16  g_vt_h[BB * CC * TT];     // vw transposed: [B][C][T]
__device__ bf16  g_vt_l[BB * CC * TT];
__device__ bf16  g_attn_h[(size_t)BB * TT * TT];
__device__ float g_h[BB * TT * CC];
// weight splits
__device__ bf16  g_wq_h[CC * EE], g_wq_l[CC * EE];     // Wq elementwise split [C,E]
__device__ bf16  g_wk_h[CC * EE], g_wk_l[CC * EE];     // Wk elementwise split [C,E]
__device__ bf16  g_wv_h[CC * EE], g_wv_l[CC * EE];     // Wv elementwise split [C,E]
__device__ bf16  g_woT_h[CC * EE], g_woT_l[CC * EE];   // Wo^T split [C,E]
// fused weight products (split)
__device__ bf16  g_MT_h[CC * CC], g_MT_l[CC * CC];     // MT = Wk @ Wq^T
__device__ bf16  g_NT_h[CC * CC], g_NT_l[CC * CC];     // NT = Wo^T @ Wv^T
// bias-correction vectors
__device__ float g_vqk[CC];     // Wq @ bk
__device__ float g_vkq[CC];     // Wk @ bq
__device__ float g_bvo[CC];     // Wo^T @ bv
__device__ float g_u[BB * TT];  // resid @ vqk + bq.bk
__device__ float g_w[BB * TT];  // resid @ vkq
__device__ float g_scal[1];     // bq . bk
__device__ float g_zero_s[1];   // stays 0

// ------------------------------------------------------------------
// low-level helpers (family-portable ISA only)
// ------------------------------------------------------------------
__device__ __forceinline__ uint32_t smem_u32(const void* p) {
    uint32_t a;
    asm("{ .reg .u64 t; cvta.to.shared.u64 t, %1; cvt.u32.u64 %0, t; }" : "=r"(a) : "l"(p));
    return a;
}

__device__ __forceinline__ uint32_t swz64(uint32_t o) { return o ^ ((o >> 3) & 0x30); }

#define CP16(dst, src) \
    asm volatile("cp.async.cg.shared.global [%0], [%1], 16;" :: "r"(dst), "l"(src))
#define CP_COMMIT() asm volatile("cp.async.commit_group;" ::: "memory")
#define CP_WAIT(n)  asm volatile("cp.async.wait_group %0;" :: "n"(n) : "memory")

__device__ __forceinline__ void ldsm4(uint32_t* r, uint32_t addr) {
    asm volatile("ldmatrix.sync.aligned.m8n8.x4.shared.b16 {%0,%1,%2,%3}, [%4];"
                 : "=r"(r[0]), "=r"(r[1]), "=r"(r[2]), "=r"(r[3]) : "r"(addr));
}

__device__ __forceinline__ void mma_bf16(float* c, const uint32_t* a,
                                         uint32_t b0, uint32_t b1) {
    asm("mma.sync.aligned.m16n8k16.row.col.f32.bf16.bf16.f32 "
        "{%0,%1,%2,%3}, {%4,%5,%6,%7}, {%8,%9}, {%0,%1,%2,%3};"
        : "+f"(c[0]), "+f"(c[1]), "+f"(c[2]), "+f"(c[3])
        : "r"(a[0]), "r"(a[1]), "r"(a[2]), "r"(a[3]), "r"(b0), "r"(b1));
}

__device__ __forceinline__ void split2(float v, bf16& h, bf16& l) {
    h = __float2bfloat16(v);
    l = __float2bfloat16(v - __bfloat162float(h));
}

// ------------------------------------------------------------------
// HMMA GEMM: D[128m x 128n] = selected terms of (Ah+Al)·(Bh+Bl)^T
// ------------------------------------------------------------------
#define TILE_B (128 * 32 * 2)
#define CHUNK_B (4 * TILE_B)
#define NSTAGE 3
#define GEMM_SMEM_REQ (NSTAGE * CHUNK_B)

enum { EPI_F32 = 0, EPI_BIAS_SPLIT = 1, EPI_BIAS_SPLIT_T = 2, EPI_SPLIT = 3,
       EPI_F32_BIAS_RES = 4, EPI_F32_UW = 5 };

template <int EPI, int USE_AL, int USE_BL>
__global__ __launch_bounds__(512)
void hmma_gemm(const bf16* __restrict__ Ah, const bf16* __restrict__ Al, int ldA, size_t sA,
               const bf16* __restrict__ Bh, const bf16* __restrict__ Bl, int ldB, size_t sB,
               const float* __restrict__ bias, const float* __restrict__ res,
               const float* __restrict__ uvec, const float* __restrict__ wvec,
               float* __restrict__ Cf, bf16* __restrict__ Ch, bf16* __restrict__ Cl,
               int ldc, size_t sC, int K) {
    extern __shared__ char sm[];
    uint32_t smu = smem_u32(sm);

    const int tid = threadIdx.x;
    const int w = tid >> 5, lane = tid & 31;
    const int bz = blockIdx.z;
    const int m0 = blockIdx.y * 128;
    const int n0 = blockIdx.x * 128;

    const bf16* pAh = Ah + (size_t)bz * sA + (size_t)m0 * ldA;
    const bf16* pAl = USE_AL ? (Al + (size_t)bz * sA + (size_t)m0 * ldA) : nullptr;
    const bf16* pBh = Bh + (size_t)bz * sB + (size_t)n0 * ldB;
    const bf16* pBl = USE_BL ? (Bl + (size_t)bz * sB + (size_t)n0 * ldB) : nullptr;

    const int lrow = tid >> 2, lcs = tid & 3;
    const uint32_t loff = swz64((uint32_t)(lrow * 64 + lcs * 16));
    auto load_chunk = [&](int buf, int k0) {
        uint32_t base = smu + (uint32_t)buf * CHUNK_B;
        CP16(base + 0 * TILE_B + loff, pAh + (size_t)lrow * ldA + k0 + lcs * 8);
        if (USE_AL) CP16(base + 1 * TILE_B + loff, pAl + (size_t)lrow * ldA + k0 + lcs * 8);
        CP16(base + 2 * TILE_B + loff, pBh + (size_t)lrow * ldB + k0 + lcs * 8);
        if (USE_BL) CP16(base + 3 * TILE_B + loff, pBl + (size_t)lrow * ldB + k0 + lcs * 8);
    };

    const int wm = w >> 2, wn = w & 3;
    const int lr = lane & 7;
    const int r8 = (lane >> 3) & 1;
    const int chi = lane >> 4;

    uint32_t offA[2][2], offB[2][2];
#pragma unroll
    for (int mt = 0; mt < 2; mt++)
#pragma unroll
        for (int ks = 0; ks < 2; ks++)
            offA[mt][ks] = swz64((uint32_t)((wm * 32 + mt * 16 + r8 * 8 + lr) * 64 + (2 * ks + chi) * 16));
#pragma unroll
    for (int nt = 0; nt < 2; nt++)
#pragma unroll
        for (int ks = 0; ks < 2; ks++)
            offB[nt][ks] = swz64((uint32_t)((wn * 32 + nt * 16 + r8 * 8 + lr) * 64 + (2 * ks + chi) * 16));

    float acc[2][4][4];
#pragma unroll
    for (int i = 0; i < 2; i++)
#pragma unroll
        for (int j = 0; j < 4; j++)
#pragma unroll
            for (int q = 0; q < 4; q++) acc[i][j][q] = 0.f;

    const int nch = K / 32;
    load_chunk(0, 0);
    CP_COMMIT();
    if (nch > 1) load_chunk(1, 32);
    CP_COMMIT();

    int buf = 0;
    for (int c = 0; c < nch; c++) {
        CP_WAIT(1);
        __syncthreads();

        if (c + 2 < nch) {
            int fb = buf + 2;
            if (fb >= NSTAGE) fb -= NSTAGE;
            load_chunk(fb, (c + 2) * 32);
        }
        CP_COMMIT();

        uint32_t bu = smu + (uint32_t)buf * CHUNK_B;
#pragma unroll
        for (int ks = 0; ks < 2; ks++) {
            uint32_t afh[2][4], afl[2][4], bfh[2][4], bfl[2][4];
#pragma unroll
            for (int mt = 0; mt < 2; mt++) {
                ldsm4(afh[mt], bu + 0 * TILE_B + offA[mt][ks]);
                if (USE_AL) ldsm4(afl[mt], bu + 1 * TILE_B + offA[mt][ks]);
            }
#pragma unroll
            for (int nt = 0; nt < 2; nt++) {
                ldsm4(bfh[nt], bu + 2 * TILE_B + offB[nt][ks]);
                if (USE_BL) ldsm4(bfl[nt], bu + 3 * TILE_B + offB[nt][ks]);
            }
#pragma unroll
            for (int mt = 0; mt < 2; mt++)
#pragma unroll
                for (int nt = 0; nt < 2; nt++) {
                    mma_bf16(acc[mt][nt * 2 + 0], afh[mt], bfh[nt][0], bfh[nt][2]);
                    mma_bf16(acc[mt][nt * 2 + 1], afh[mt], bfh[nt][1], bfh[nt][3]);
                }
            if (USE_BL) {
#pragma unroll
                for (int mt = 0; mt < 2; mt++)
#pragma unroll
                    for (int nt = 0; nt < 2; nt++) {
                        mma_bf16(acc[mt][nt * 2 + 0], afh[mt], bfl[nt][0], bfl[nt][2]);
                        mma_bf16(acc[mt][nt * 2 + 1], afh[mt], bfl[nt][1], bfl[nt][3]);
                    }
            }
            if (USE_AL) {
#pragma unroll
                for (int mt = 0; mt < 2; mt++)
#pragma unroll
                    for (int nt = 0; nt < 2; nt++) {
                        mma_bf16(acc[mt][nt * 2 + 0], afl[mt], bfh[nt][0], bfh[nt][2]);
                        mma_bf16(acc[mt][nt * 2 + 1], afl[mt], bfh[nt][1], bfh[nt][3]);
                    }
            }
        }
        buf++;
        if (buf == NSTAGE) buf = 0;
    }
    __syncthreads();

    // ---- epilogue: accumulators -> staged smem [128][129] fp32 -> gmem ----
    float* st = (float*)sm;
    {
        int g = lane >> 2, t4 = lane & 3;
#pragma unroll
        for (int mt = 0; mt < 2; mt++) {
            int r = wm * 32 + mt * 16 + g;
#pragma unroll
            for (int j = 0; j < 4; j++) {
                int ccol = wn * 32 + j * 8 + 2 * t4;
                st[r * 129 + ccol]           = acc[mt][j][0];
                st[r * 129 + ccol + 1]       = acc[mt][j][1];
                st[(r + 8) * 129 + ccol]     = acc[mt][j][2];
                st[(r + 8) * 129 + ccol + 1] = acc[mt][j][3];
            }
        }
    }
    __syncthreads();

    if (EPI == EPI_BIAS_SPLIT_T) {
        // transposed split store: dest [b][c][t] (ld = TT within batch of CC rows)
#pragma unroll 4
        for (int it = 0; it < 8; it++) {
            int col = w + 16 * it;
            float bv = bias[n0 + col];
#pragma unroll
            for (int j = 0; j < 4; j++) {
                int row = lane + 32 * j;
                float v = st[row * 129 + col] + bv;
                size_t m = (size_t)m0 + row;
                int bb_ = (int)(m / TT);
                int t = (int)(m % TT);
                size_t off = ((size_t)bb_ * CC + (n0 + col)) * TT + t;
                bf16 h, l; split2(v, h, l);
                Ch[off] = h;
                Cl[off] = l;
            }
        }
    } else if (EPI == EPI_F32_UW) {
#pragma unroll 2
        for (int rr = 0; rr < 8; rr++) {
            int row = w * 8 + rr;
            size_t m = (size_t)m0 + row;
            float um = uvec[(size_t)bz * TT + m];
#pragma unroll
            for (int cb = 0; cb < 4; cb++) {
                int col = lane + 32 * cb;
                float wn_ = wvec[(size_t)bz * TT + n0 + col];
                float v = st[row * 129 + col] + um + wn_;
                Cf[(size_t)bz * sC + m * ldc + n0 + col] = v;
            }
        }
    } else {
        float bv[4];
#pragma unroll
        for (int cb = 0; cb < 4; cb++)
            bv[cb] = (EPI == EPI_BIAS_SPLIT || EPI == EPI_F32_BIAS_RES) ? bias[n0 + lane + 32 * cb] : 0.f;
        const float* resb = (EPI == EPI_F32_BIAS_RES) ? (res + (size_t)bz * sC) : nullptr;

#pragma unroll 2
        for (int rr = 0; rr < 8; rr++) {
            int row = w * 8 + rr;
            size_t m = (size_t)m0 + row;
#pragma unroll
            for (int cb = 0; cb < 4; cb++) {
                int col = lane + 32 * cb;
                float v = st[row * 129 + col] + bv[cb];
                size_t off = (size_t)bz * sC + m * ldc + n0 + col;
                if (EPI == EPI_F32) {
                    Cf[off] = v;
                } else if (EPI == EPI_F32_BIAS_RES) {
                    Cf[off] = v + resb[m * ldc + n0 + col];
                } else {
                    bf16 h, l; split2(v, h, l);
                    Ch[off] = h;
                    Cl[off] = l;
                }
            }
        }
    }
}

// ------------------------------------------------------------------
// transpose + split: x[B,C,T] -> resid[B,T,C] (fp32 + hi/lo bf16)
// ------------------------------------------------------------------
__global__ __launch_bounds__(256)
void transpose_split(const float* __restrict__ x, float* __restrict__ r,
                     bf16* __restrict__ rh, bf16* __restrict__ rl) {
    __shared__ float tile[32][33];
    int b = blockIdx.z;
    int t0 = blockIdx.x * 32;
    int c0 = blockIdx.y * 32;
    const float* xb = x + (size_t)b * CC * TT;
    size_t ob = (size_t)b * TT * CC;
    int tx = threadIdx.x, ty = threadIdx.y;
#pragma unroll
    for (int i = ty; i < 32; i += 8)
        tile[i][tx] = xb[(size_t)(c0 + i) * TT + t0 + tx];
    __syncthreads();
#pragma unroll
    for (int i = ty; i < 32; i += 8) {
        float v = tile[tx][i];
        size_t off = ob + (size_t)(t0 + i) * CC + c0 + tx;
        r[off] = v;
        bf16 h, l; split2(v, h, l);
        rh[off] = h;
        rl[off] = l;
    }
}

// elementwise split W [512*512]
__global__ __launch_bounds__(256)
void splitW(const float* __restrict__ W, bf16* __restrict__ Th, bf16* __restrict__ Tl) {
    int i = blockIdx.x * 256 + threadIdx.x;
    float v = W[i];
    bf16 h, l; split2(v, h, l);
    Th[i] = h;
    Tl[i] = l;
}

// W [512,512] -> W^T hi/lo [512,512] (used for Wo)
__global__ __launch_bounds__(256)
void wsplit(const float* __restrict__ W, bf16* __restrict__ Th, bf16* __restrict__ Tl) {
    __shared__ float tile[32][33];
    int k0 = blockIdx.y * 32, n0 = blockIdx.x * 32;
    int tx = threadIdx.x, ty = threadIdx.y;
#pragma unroll
    for (int i = ty; i < 32; i += 8)
        tile[i][tx] = W[(size_t)(k0 + i) * 512 + n0 + tx];
    __syncthreads();
#pragma unroll
    for (int i = ty; i < 32; i += 8) {
        float v = tile[tx][i];
        size_t off = (size_t)(n0 + i) * 512 + k0 + tx;
        bf16 h, l; split2(v, h, l);
        Th[off] = h;
        Tl[off] = l;
    }
}

// ---- small bias-path kernels (exact handling of bq/bk/bv) ----
__global__ void dotk(const float* __restrict__ a, const float* __restrict__ b,
                     float* __restrict__ outscal) {
    int lane = threadIdx.x;
    float s = 0.f;
    for (int i = lane; i < 512; i += 32) s += a[i] * b[i];
#pragma unroll
    for (int o = 16; o; o >>= 1) s += __shfl_xor_sync(0xffffffffu, s, o);
    if (lane == 0) outscal[0] = s;
}

// out[c] = sum_e A[c,e]*v[e]   (A fp32 row-major [512,512])
__global__ __launch_bounds__(256)
void matvec_row(const float* __restrict__ A, const float* __restrict__ v,
                float* __restrict__ out) {
    int c = blockIdx.x * 8 + (threadIdx.x >> 5);
    int lane = threadIdx.x & 31;
    float s = 0.f;
    for (int e = lane; e < 512; e += 32) s += A[(size_t)c * 512 + e] * v[e];
#pragma unroll
    for (int o = 16; o; o >>= 1) s += __shfl_xor_sync(0xffffffffu, s, o);
    if (lane == 0) out[c] = s;
}

// out[c] = sum_e (Th+Tl)[c,e]*v[e]   (split bf16 rows; used for Wo^T @ bv)
__global__ __launch_bounds__(256)
void matvec_row_bf(const bf16* __restrict__ Th, const bf16* __restrict__ Tl,
                   const float* __restrict__ v, float* __restrict__ out) {
    int c = blockIdx.x * 8 + (threadIdx.x >> 5);
    int lane = threadIdx.x & 31;
    float s = 0.f;
    for (int e = lane; e < 512; e += 32) {
        float wv = __bfloat162float(Th[(size_t)c * 512 + e]) +
                   __bfloat162float(Tl[(size_t)c * 512 + e]);
        s += wv * v[e];
    }
#pragma unroll
    for (int o = 16; o; o >>= 1) s += __shfl_xor_sync(0xffffffffu, s, o);
    if (lane == 0) out[c] = s;
}

// u[i] = sum_c r[i,c]*vv[c] + scal[0]
__global__ __launch_bounds__(256)
void rowdot(const float* __restrict__ r, const float* __restrict__ vv,
            const float* __restrict__ scal, float* __restrict__ u) {
    int row = blockIdx.x * 8 + (threadIdx.x >> 5);
    int lane = threadIdx.x & 31;
    float s = 0.f;
    for (int c = lane; c < 512; c += 32) s += r[(size_t)row * 512 + c] * vv[c];
#pragma unroll
    for (int o = 16; o; o >>= 1) s += __shfl_xor_sync(0xffffffffu, s, o);
    if (lane == 0) u[row] = s + scal[0];
}

// ------------------------------------------------------------------
// softmax (in-place fp32) + emit hi bf16 only
// ------------------------------------------------------------------
__global__ __launch_bounds__(256)
void softmax_split(float* __restrict__ attn, bf16* __restrict__ ah) {
    size_t ro = (size_t)blockIdx.x * TT;
    float* row = attn + ro;
    int t = threadIdx.x;
    float vals[8];
    float m = -1e30f;
#pragma unroll
    for (int j = 0; j < 8; j++) {
        vals[j] = row[t + 256 * j];
        m = fmaxf(m, vals[j]);
    }
#pragma unroll
    for (int o = 16; o; o >>= 1) m = fmaxf(m, __shfl_xor_sync(0xffffffffu, m, o));
    __shared__ float smax[8], ssum[8];
    if ((t & 31) == 0) smax[t >> 5] = m;
    __syncthreads();
    float rm = smax[0];
#pragma unroll
    for (int i = 1; i < 8; i++) rm = fmaxf(rm, smax[i]);

    float s = 0.f;
#pragma unroll
    for (int j = 0; j < 8; j++) {
        vals[j] = expf(vals[j] - rm);
        s += vals[j];
    }
#pragma unroll
    for (int o = 16; o; o >>= 1) s += __shfl_xor_sync(0xffffffffu, s, o);
    if ((t & 31) == 0) ssum[t >> 5] = s;
    __syncthreads();
    float tot = 0.f;
#pragma unroll
    for (int i = 0; i < 8; i++) tot += ssum[i];
    float inv = 1.f / tot;

#pragma unroll
    for (int j = 0; j < 8; j++) {
        float v = vals[j] * inv;
        row[t + 256 * j] = v;
        ah[ro + t + 256 * j] = __float2bfloat16(v);
    }
}

// ------------------------------------------------------------------
// LayerNorm over C=512
// ------------------------------------------------------------------
__global__ __launch_bounds__(128)
void ln_kernel(const float* __restrict__ h, const float* __restrict__ gamma,
               const float* __restrict__ beta, float* __restrict__ out) {
    const float* hr = h + (size_t)blockIdx.x * CC;
    int t = threadIdx.x;
    float4 v = ((const float4*)hr)[t];

    float s = v.x + v.y + v.z + v.w;
#pragma unroll
    for (int o = 16; o; o >>= 1) s += __shfl_xor_sync(0xffffffffu, s, o);
    __shared__ float s1[4], s2[4];
    if ((t & 31) == 0) s1[t >> 5] = s;
    __syncthreads();
    float mu = (s1[0] + s1[1] + s1[2] + s1[3]) * (1.f / CC);

    float dx = v.x - mu, dy = v.y - mu, dz = v.z - mu, dw = v.w - mu;
    float q = dx * dx + dy * dy + dz * dz + dw * dw;
#pragma unroll
    for (int o = 16; o; o >>= 1) q += __shfl_xor_sync(0xffffffffu, q, o);
    if ((t & 31) == 0) s2[t >> 5] = q;
    __syncthreads();
    float var = (s2[0] + s2[1] + s2[2] + s2[3]) * (1.f / CC);
    float inv = rsqrtf(var + LN_EPS);

    float4 g = ((const float4*)gamma)[t];
    float4 b = ((const float4*)beta)[t];
    float4 o4;
    o4.x = dx * inv * g.x + b.x;
    o4.y = dy * inv * g.y + b.y;
    o4.z = dz * inv * g.z + b.z;
    o4.w = dw * inv * g.w + b.w;
    ((float4*)(out + (size_t)blockIdx.x * CC))[t] = o4;
}

// ------------------------------------------------------------------
// launch
// ------------------------------------------------------------------
extern "C" void kernel_launch(void* const* d_in, const int* in_sizes, int n_in,
                              void* d_out, int out_size) {
    const float* x     = (const float*)d_in[0];
    const float* Wq    = (const float*)d_in[1];
    const float* bq    = (const float*)d_in[2];
    const float* Wk    = (const float*)d_in[3];
    const float* bk    = (const float*)d_in[4];
    const float* Wv    = (const float*)d_in[5];
    const float* bv    = (const float*)d_in[6];
    const float* Wo    = (const float*)d_in[7];
    const float* bo    = (const float*)d_in[8];
    const float* gamma = (const float*)d_in[9];
    const float* beta  = (const float*)d_in[10];

    float* out = (float*)d_out;
    float* attn = out;
    float* final_out = out + (size_t)BB * TT * TT;

    float *resid, *hbuf, *vqk, *vkq, *bvo, *uv, *wv_, *scal, *zero_s;
    bf16 *rh, *rl, *qmh, *qml, *vth, *vtl, *anh;
    bf16 *wqh, *wql, *wkh, *wkl, *wvh, *wvl, *woh, *wol;
    bf16 *mth, *mtl, *nth, *ntl;
    cudaGetSymbolAddress((void**)&resid, g_resid);
    cudaGetSymbolAddress((void**)&hbuf, g_h);
    cudaGetSymbolAddress((void**)&rh, g_resid_h);
    cudaGetSymbolAddress((void**)&rl, g_resid_l);
    cudaGetSymbolAddress((void**)&qmh, g_qm_h);
    cudaGetSymbolAddress((void**)&qml, g_qm_l);
    cudaGetSymbolAddress((void**)&vth, g_vt_h);
    cudaGetSymbolAddress((void**)&vtl, g_vt_l);
    cudaGetSymbolAddress((void**)&anh, g_attn_h);
    cudaGetSymbolAddress((void**)&wqh, g_wq_h);
    cudaGetSymbolAddress((void**)&wql, g_wq_l);
    cudaGetSymbolAddress((void**)&wkh, g_wk_h);
    cudaGetSymbolAddress((void**)&wkl, g_wk_l);
    cudaGetSymbolAddress((void**)&wvh, g_wv_h);
    cudaGetSymbolAddress((void**)&wvl, g_wv_l);
    cudaGetSymbolAddress((void**)&woh, g_woT_h);
    cudaGetSymbolAddress((void**)&wol, g_woT_l);
    cudaGetSymbolAddress((void**)&mth, g_MT_h);
    cudaGetSymbolAddress((void**)&mtl, g_MT_l);
    cudaGetSymbolAddress((void**)&nth, g_NT_h);
    cudaGetSymbolAddress((void**)&ntl, g_NT_l);
    cudaGetSymbolAddress((void**)&vqk, g_vqk);
    cudaGetSymbolAddress((void**)&vkq, g_vkq);
    cudaGetSymbolAddress((void**)&bvo, g_bvo);
    cudaGetSymbolAddress((void**)&uv, g_u);
    cudaGetSymbolAddress((void**)&wv_, g_w);
    cudaGetSymbolAddress((void**)&scal, g_scal);
    cudaGetSymbolAddress((void**)&zero_s, g_zero_s);

    cudaFuncSetAttribute(hmma_gemm<EPI_SPLIT, 1, 1>,        cudaFuncAttributeMaxDynamicSharedMemorySize, GEMM_SMEM_REQ);
    cudaFuncSetAttribute(hmma_gemm<EPI_F32_UW, 1, 1>,       cudaFuncAttributeMaxDynamicSharedMemorySize, GEMM_SMEM_REQ);
    cudaFuncSetAttribute(hmma_gemm<EPI_BIAS_SPLIT_T, 0, 1>, cudaFuncAttributeMaxDynamicSharedMemorySize, GEMM_SMEM_REQ);
    cudaFuncSetAttribute(hmma_gemm<EPI_F32_BIAS_RES, 0, 1>, cudaFuncAttributeMaxDynamicSharedMemorySize, GEMM_SMEM_REQ);

    // ---- prep: transpose + weight splits ----
    transpose_split<<<dim3(TT / 32, CC / 32, BB), dim3(32, 8)>>>(x, resid, rh, rl);
    splitW<<<1024, 256>>>(Wq, wqh, wql);
    splitW<<<1024, 256>>>(Wk, wkh, wkl);
    splitW<<<1024, 256>>>(Wv, wvh, wvl);
    wsplit<<<dim3(16, 16), dim3(32, 8)>>>(Wo, woh, wol);

    // bias-correction vectors (exact): vqk = Wq@bk, vkq = Wk@bq, bvo = Wo^T@bv, scal = bq.bk
    dotk<<<1, 32>>>(bq, bk, scal);
    matvec_row<<<64, 256>>>(Wq, bk, vqk);
    matvec_row<<<64, 256>>>(Wk, bq, vkq);
    matvec_row_bf<<<64, 256>>>(woh, wol, bv, bvo);
    rowdot<<<(BB * TT) / 8, 256>>>(resid, vqk, scal, uv);     // u = r@vqk + bq.bk
    rowdot<<<(BB * TT) / 8, 256>>>(resid, vkq, zero_s, wv_);  // w = r@vkq

    // MT = Wk @ Wq^T  (for energy), NT = Wo^T @ Wv^T (for out path) — tiny GEMMs
    hmma_gemm<EPI_SPLIT, 1, 1><<<dim3(4, 4, 1), 512, GEMM_SMEM_REQ>>>(
        wkh, wkl, EE, 0, wqh, wql, EE, 0, nullptr, nullptr, nullptr, nullptr,
        nullptr, mth, mtl, CC, 0, EE);
    hmma_gemm<EPI_SPLIT, 1, 1><<<dim3(4, 4, 1), 512, GEMM_SMEM_REQ>>>(
        woh, wol, EE, 0, wvh, wvl, EE, 0, nullptr, nullptr, nullptr, nullptr,
        nullptr, nth, ntl, CC, 0, EE);

    // qm = resid @ M   (3-term, split out)
    hmma_gemm<EPI_SPLIT, 1, 1><<<dim3(CC / 128, (BB * TT) / 128, 1), 512, GEMM_SMEM_REQ>>>(
        rh, rl, CC, 0, mth, mtl, CC, 0, nullptr, nullptr, nullptr, nullptr,
        nullptr, qmh, qml, CC, 0, CC);

    // energy = qm @ resid^T + u[t] + w[s] + bq.bk  -> fp32 logits in attn region
    hmma_gemm<EPI_F32_UW, 1, 1><<<dim3(TT / 128, TT / 128, BB), 512, GEMM_SMEM_REQ>>>(
        qmh, qml, CC, (size_t)TT * CC, rh, rl, CC, (size_t)TT * CC,
        nullptr, nullptr, uv, wv_,
        attn, nullptr, nullptr, TT, (size_t)TT * TT, CC);

    // softmax in-place + emit hi bf16
    softmax_split<<<BB * TT, 256>>>(attn, anh);

    // vw = resid @ N + bvo   (2-term, transposed split out -> [B][C][T])
    hmma_gemm<EPI_BIAS_SPLIT_T, 0, 1><<<dim3(CC / 128, (BB * TT) / 128, 1), 512, GEMM_SMEM_REQ>>>(
        rh, nullptr, CC, 0, nth, ntl, CC, 0, bvo, nullptr, nullptr, nullptr,
        nullptr, vth, vtl, CC, 0, CC);

    // h = attn_hi @ vw^T + bo + resid   (2-term)
    hmma_gemm<EPI_F32_BIAS_RES, 0, 1><<<dim3(CC / 128, TT / 128, BB), 512, GEMM_SMEM_REQ>>>(
        anh, nullptr, TT, (size_t)TT * TT, vth, vtl, TT, (size_t)CC * TT,
        bo, resid, nullptr, nullptr,
        hbuf, nullptr, nullptr, CC, (size_t)TT * CC, TT);

    // LayerNorm -> final output region
    ln_kernel<<<BB * TT, 128>>>(hbuf, gamma, beta, final_out);
}